// round 3
// baseline (speedup 1.0000x reference)
#include <cuda_runtime.h>

#define B_     4
#define L_     256
#define NNODE  1024
#define DNODE  256
#define DPAIR  128
#define NE     65536
#define M0_    32
#define DIRR   56
#define WNUM_  1664

// TP constants
#define PW0   0.15811388300841897f   // sqrt(1/40)
#define PW1   0.25f
#define S3C   0.5773502691896258f    // 1/sqrt(3)
#define F121  0.5477225575051661f    // sqrt(3/10)

// small device scratch (no allocations allowed)
__device__ float g_feats[NNODE * DIRR];
__device__ float g_sums [NNODE * DIRR];
__device__ float g_cnt  [NNODE];

// ---------------------------------------------------------------------------
// prep: feats = [node@proj_l0_w + b, l1_feats]; zero accumulators
// total work items: 32768 (l0) + 24576 (l1 copy) + 57344 (zero sums) + 1024
// ---------------------------------------------------------------------------
__global__ void prep_kernel(const float* __restrict__ node,
                            const float* __restrict__ pl0w,
                            const float* __restrict__ pl0b,
                            const float* __restrict__ l1) {
    int gtid = blockIdx.x * blockDim.x + threadIdx.x;
    const int T0 = NNODE * M0_;            // 32768
    const int T1 = T0 + NNODE * 24;        // +24576
    const int T2 = T1 + NNODE * DIRR;      // +57344
    const int T3 = T2 + NNODE;             // +1024
    if (gtid < T0) {
        int n = gtid >> 5, u = gtid & 31;
        const float* nr = node + n * DNODE;
        float acc = pl0b[u];
#pragma unroll 4
        for (int k = 0; k < DNODE; ++k) acc += nr[k] * pl0w[k * M0_ + u];
        g_feats[n * DIRR + u] = acc;
    } else if (gtid < T1) {
        int t = gtid - T0; int n = t / 24, m = t - n * 24;
        g_feats[n * DIRR + M0_ + m] = l1[n * 24 + m];
    } else if (gtid < T2) {
        g_sums[gtid - T1] = 0.f;
    } else if (gtid < T3) {
        g_cnt[gtid - T2] = 0.f;
    }
}

// ---------------------------------------------------------------------------
// main fused kernel: 64 edges per CTA, 256 threads.
// stage 0: gather pair rows + fc1_w to smem
// stage 1: LayerNorm + fc1 + relu -> h[64][129] (h[.][128]=1 carries fc2_b)
// stage 2: 184 TP left-coefficients A per edge
// stage 3: j-chunk loop over fc2_w: conv accumulation fully in registers
// epilogue: atomicAdd into g_sums / g_cnt
// ---------------------------------------------------------------------------
__launch_bounds__(256, 1)
__global__ void e3_main_kernel(const float* __restrict__ pair,
                               const int*   __restrict__ pair_index,
                               const float* __restrict__ edge_sh,
                               const int*   __restrict__ edge_src,
                               const int*   __restrict__ edge_dst,
                               const float* __restrict__ ln_g,
                               const float* __restrict__ ln_b,
                               const float* __restrict__ fc1_w,
                               const float* __restrict__ fc1_b,
                               const float* __restrict__ fc2_w,
                               const float* __restrict__ fc2_b) {
    extern __shared__ float smem[];
    float* sh_h  = smem;                       // 64*129 = 8256
    float* sh_A  = smem + 64 * 129;            // 64*184 = 11776 (x staging first)
    float* sh_fw = smem + 64 * 129 + 64 * 184; // 16384

    const int tid  = threadIdx.x;
    const int eb0  = blockIdx.x * 64;
    const int w    = tid >> 5, lane = tid & 31;

    // ---- stage 0: gather x (pitch 128, lives in sh_A area) + fc1_w --------
    for (int idx = tid; idx < 64 * 128; idx += 256) {
        int el = idx >> 7, col = idx & 127;
        int e = eb0 + el;
        int b = pair_index[e];
        int i = pair_index[NE + e];
        int j = pair_index[2 * NE + e];
        sh_A[el * 128 + col] = pair[(((b * L_) + i) * L_ + j) * DPAIR + col];
    }
    for (int idx = tid; idx < 4096; idx += 256)
        reinterpret_cast<float4*>(sh_fw)[idx] =
            reinterpret_cast<const float4*>(fc1_w)[idx];
    __syncthreads();

    // ---- stage 1: LN (warp per edge) --------------------------------------
    for (int ee = 0; ee < 8; ++ee) {
        float* xr = sh_A + (w * 8 + ee) * 128;
        float x0 = xr[lane], x1 = xr[lane + 32], x2 = xr[lane + 64], x3 = xr[lane + 96];
        float s = x0 + x1 + x2 + x3;
#pragma unroll
        for (int o = 16; o > 0; o >>= 1) s += __shfl_xor_sync(0xffffffffu, s, o);
        float mu = s * (1.f / 128.f);
        float d0 = x0 - mu, d1 = x1 - mu, d2 = x2 - mu, d3 = x3 - mu;
        float q = d0 * d0 + d1 * d1 + d2 * d2 + d3 * d3;
#pragma unroll
        for (int o = 16; o > 0; o >>= 1) q += __shfl_xor_sync(0xffffffffu, q, o);
        float rstd = rsqrtf(q * (1.f / 128.f) + 1e-5f);
        xr[lane]      = d0 * rstd * ln_g[lane]      + ln_b[lane];
        xr[lane + 32] = d1 * rstd * ln_g[lane + 32] + ln_b[lane + 32];
        xr[lane + 64] = d2 * rstd * ln_g[lane + 64] + ln_b[lane + 64];
        xr[lane + 96] = d3 * rstd * ln_g[lane + 96] + ln_b[lane + 96];
        if (lane == 0) sh_h[(w * 8 + ee) * 129 + 128] = 1.f;  // bias row of h
    }
    __syncwarp();

    // ---- fc1 + relu: 2 edges per pass, lane owns 4 output cols ------------
    {
        float4 b4 = *reinterpret_cast<const float4*>(fc1_b + lane * 4);
        for (int p = 0; p < 4; ++p) {
            int e0 = w * 8 + p * 2, e1 = e0 + 1;
            const float* xa = sh_A + e0 * 128;
            const float* xb = sh_A + e1 * 128;
            float a00 = b4.x, a01 = b4.y, a02 = b4.z, a03 = b4.w;
            float a10 = b4.x, a11 = b4.y, a12 = b4.z, a13 = b4.w;
#pragma unroll 4
            for (int i = 0; i < 128; ++i) {
                float va = xa[i], vb = xb[i];
                float4 f = *reinterpret_cast<const float4*>(&sh_fw[i * 128 + lane * 4]);
                a00 += va * f.x; a01 += va * f.y; a02 += va * f.z; a03 += va * f.w;
                a10 += vb * f.x; a11 += vb * f.y; a12 += vb * f.z; a13 += vb * f.w;
            }
            float* h0 = sh_h + e0 * 129 + lane * 4;
            float* h1 = sh_h + e1 * 129 + lane * 4;
            h0[0] = fmaxf(a00, 0.f); h0[1] = fmaxf(a01, 0.f);
            h0[2] = fmaxf(a02, 0.f); h0[3] = fmaxf(a03, 0.f);
            h1[0] = fmaxf(a10, 0.f); h1[1] = fmaxf(a11, 0.f);
            h1[2] = fmaxf(a12, 0.f); h1[3] = fmaxf(a13, 0.f);
        }
    }
    __syncthreads();   // everyone done reading x in sh_A

    // ---- stage 2: left-coefficients A[e][184] -----------------------------
    // layout per edge: [0:32)=A1, [32:40)=A4, [40:136)=A2[u*3+m],
    //                  [136:160)=A3[u*3+m], [160:184)=A5[u*3+m]
    for (int idx = tid; idx < 64 * 184; idx += 256) {
        int el = idx / 184, a = idx - el * 184;
        int e  = eb0 + el;
        const float* F  = g_feats + edge_dst[e] * DIRR;
        const float* SH = edge_sh + e * 9;
        float val;
        if (a < 32) {
            val = PW0 * F[a] * SH[0];
        } else if (a < 40) {
            int u = a - 32;
            val = (PW0 * S3C) * (F[32 + u * 3] * SH[1] + F[33 + u * 3] * SH[2]
                                 + F[34 + u * 3] * SH[3]);
        } else if (a < 136) {
            int t = a - 40; int u = t / 3, m = t - u * 3;
            val = (PW1 * S3C) * F[u] * SH[1 + m];
        } else if (a < 160) {
            int t = a - 136; int u = t / 3, m = t - u * 3;
            val = (PW1 * S3C) * F[32 + u * 3 + m] * SH[0];
        } else {
            int t = a - 160; int u = t / 3, m = t - u * 3;
            float xx = F[32 + u * 3], xy = F[33 + u * 3], xz = F[34 + u * 3];
            float s0 = SH[4], s1 = SH[5], s2 = SH[6], s3v = SH[7], s4 = SH[8];
            float t5;
            if (m == 0)      t5 = (xz * s0 + xy * s1 - xx * s4) * S3C - xx * s2 * (1.f / 3.f);
            else if (m == 1) t5 = (xx * s1 + xz * s3v) * S3C + xy * s2 * (2.f / 3.f);
            else             t5 = (xx * s0 + xy * s3v + xz * s4) * S3C - xz * s2 * (1.f / 3.f);
            val = (PW1 * F121) * t5;
        }
        sh_A[el * 184 + a] = val;
    }

    // ---- stage 3: fc2 chunk loop fused with TP contraction ----------------
    float acc14[8];
#pragma unroll
    for (int g = 0; g < 8; ++g) acc14[g] = 0.f;
    float acc2a[3] = {0.f, 0.f, 0.f};
    float acc2b[3] = {0.f, 0.f, 0.f};
    const int v  = tid & 31, eg = tid >> 5;   // out0 mapping: edge g*8+eg, col v
    const int v8 = tid & 7,  e8 = tid >> 3;   // out1 mapping: edges e8 / 32+e8, w-col v8

    for (int j0 = 0; j0 < 129; j0 += 8) {
        const int jcnt = (129 - j0) < 8 ? (129 - j0) : 8;
        __syncthreads();
        {   // cooperative load of fc2_w chunk (+bias row as j==128)
            const int n4 = jcnt * 416;
            for (int t = tid; t < n4; t += 256) {
                const int jj = t / 416, k4 = t - jj * 416;
                const int jg = j0 + jj;
                float4 val = (jg < 128)
                    ? reinterpret_cast<const float4*>(fc2_w)[jg * 416 + k4]
                    : reinterpret_cast<const float4*>(fc2_b)[k4];
                reinterpret_cast<float4*>(sh_fw)[jj * 416 + k4] = val;
            }
        }
        __syncthreads();

        // h chunk registers (broadcast loads; zero-padded past jcnt)
        float hr[8][8];
#pragma unroll
        for (int g = 0; g < 8; ++g) {
#pragma unroll
            for (int jj = 0; jj < 8; ++jj)
                hr[g][jj] = (jj < jcnt) ? sh_h[(g * 8 + eg) * 129 + j0 + jj] : 0.f;
        }

        // region W1: k = u*32+v -> out0[v], coeff A1[u]
        for (int u = 0; u < 32; ++u) {
            float f[8];
#pragma unroll
            for (int jj = 0; jj < 8; ++jj) f[jj] = sh_fw[jj * WNUM_ + u * 32 + v];
#pragma unroll
            for (int g = 0; g < 8; ++g) {
                float wp = 0.f;
#pragma unroll
                for (int jj = 0; jj < 8; ++jj) wp += hr[g][jj] * f[jj];
                acc14[g] += sh_A[(g * 8 + eg) * 184 + u] * wp;
            }
        }
        // region W4: k = 1344+u*32+v -> out0[v], coeff A4[u]
        for (int u = 0; u < 8; ++u) {
            float f[8];
#pragma unroll
            for (int jj = 0; jj < 8; ++jj) f[jj] = sh_fw[jj * WNUM_ + 1344 + u * 32 + v];
#pragma unroll
            for (int g = 0; g < 8; ++g) {
                float wp = 0.f;
#pragma unroll
                for (int jj = 0; jj < 8; ++jj) wp += hr[g][jj] * f[jj];
                acc14[g] += sh_A[(g * 8 + eg) * 184 + 32 + u] * wp;
            }
        }

        // h chunks for out1 mapping (2 edges per thread)
        float ha[8], hb[8];
#pragma unroll
        for (int jj = 0; jj < 8; ++jj) {
            ha[jj] = (jj < jcnt) ? sh_h[e8 * 129 + j0 + jj]        : 0.f;
            hb[jj] = (jj < jcnt) ? sh_h[(32 + e8) * 129 + j0 + jj] : 0.f;
        }
        // region W2: k = 1024+u*8+v8 -> out1[v8][m], coeff A2[u][m]
        for (int u = 0; u < 32; ++u) {
            float f[8];
#pragma unroll
            for (int jj = 0; jj < 8; ++jj) f[jj] = sh_fw[jj * WNUM_ + 1024 + u * 8 + v8];
            float wpa = 0.f, wpb = 0.f;
#pragma unroll
            for (int jj = 0; jj < 8; ++jj) { wpa += ha[jj] * f[jj]; wpb += hb[jj] * f[jj]; }
            const float* Aa = sh_A + e8 * 184 + 40 + u * 3;
            const float* Ab = sh_A + (32 + e8) * 184 + 40 + u * 3;
            acc2a[0] += Aa[0] * wpa; acc2a[1] += Aa[1] * wpa; acc2a[2] += Aa[2] * wpa;
            acc2b[0] += Ab[0] * wpb; acc2b[1] += Ab[1] * wpb; acc2b[2] += Ab[2] * wpb;
        }
        // region W3: k = 1280+u*8+v8, coeff A3[u][m]
        for (int u = 0; u < 8; ++u) {
            float f[8];
#pragma unroll
            for (int jj = 0; jj < 8; ++jj) f[jj] = sh_fw[jj * WNUM_ + 1280 + u * 8 + v8];
            float wpa = 0.f, wpb = 0.f;
#pragma unroll
            for (int jj = 0; jj < 8; ++jj) { wpa += ha[jj] * f[jj]; wpb += hb[jj] * f[jj]; }
            const float* Aa = sh_A + e8 * 184 + 136 + u * 3;
            const float* Ab = sh_A + (32 + e8) * 184 + 136 + u * 3;
            acc2a[0] += Aa[0] * wpa; acc2a[1] += Aa[1] * wpa; acc2a[2] += Aa[2] * wpa;
            acc2b[0] += Ab[0] * wpb; acc2b[1] += Ab[1] * wpb; acc2b[2] += Ab[2] * wpb;
        }
        // region W5: k = 1600+u*8+v8, coeff A5[u][m]
        for (int u = 0; u < 8; ++u) {
            float f[8];
#pragma unroll
            for (int jj = 0; jj < 8; ++jj) f[jj] = sh_fw[jj * WNUM_ + 1600 + u * 8 + v8];
            float wpa = 0.f, wpb = 0.f;
#pragma unroll
            for (int jj = 0; jj < 8; ++jj) { wpa += ha[jj] * f[jj]; wpb += hb[jj] * f[jj]; }
            const float* Aa = sh_A + e8 * 184 + 160 + u * 3;
            const float* Ab = sh_A + (32 + e8) * 184 + 160 + u * 3;
            acc2a[0] += Aa[0] * wpa; acc2a[1] += Aa[1] * wpa; acc2a[2] += Aa[2] * wpa;
            acc2b[0] += Ab[0] * wpb; acc2b[1] += Ab[1] * wpb; acc2b[2] += Ab[2] * wpb;
        }
    }

    // ---- epilogue: scatter-add ----
#pragma unroll
    for (int g = 0; g < 8; ++g) {
        int e = eb0 + g * 8 + eg;
        atomicAdd(&g_sums[edge_src[e] * DIRR + v], acc14[g]);
    }
    {
        int s1 = edge_src[eb0 + e8];
        int s2 = edge_src[eb0 + 32 + e8];
#pragma unroll
        for (int m = 0; m < 3; ++m) {
            atomicAdd(&g_sums[s1 * DIRR + 32 + v8 * 3 + m], acc2a[m]);
            atomicAdd(&g_sums[s2 * DIRR + 32 + v8 * 3 + m], acc2b[m]);
        }
    }
    if (tid < 64) atomicAdd(&g_cnt[edge_src[eb0 + tid]], 1.f);
}

// ---------------------------------------------------------------------------
// finalize: mean, node projection + residuals, write outputs
// out layout: [node_new (1024*256)] then [l1_new (1024*24)]
// ---------------------------------------------------------------------------
__global__ void finalize_kernel(const float* __restrict__ node,
                                const float* __restrict__ l1,
                                const float* __restrict__ pnw,
                                const float* __restrict__ pnb,
                                float* __restrict__ out) {
    int n = blockIdx.x;
    __shared__ float o0[32];
    float inv = 1.f / fmaxf(g_cnt[n], 1.f);
    if (threadIdx.x < 32) o0[threadIdx.x] = g_sums[n * DIRR + threadIdx.x] * inv;
    __syncthreads();
    int d = threadIdx.x;
    float acc = pnb[d];
#pragma unroll
    for (int u = 0; u < 32; ++u) acc += o0[u] * pnw[u * DNODE + d];
    out[n * DNODE + d] = acc + node[n * DNODE + d];
    if (d < 24)
        out[NNODE * DNODE + n * 24 + d] = g_sums[n * DIRR + 32 + d] * inv + l1[n * 24 + d];
}

// ---------------------------------------------------------------------------
extern "C" void kernel_launch(void* const* d_in, const int* in_sizes, int n_in,
                              void* d_out, int out_size) {
    const float* node = (const float*)d_in[0];
    const float* pair = (const float*)d_in[1];
    const float* l1   = (const float*)d_in[2];
    const float* esh  = (const float*)d_in[3];
    const float* pl0w = (const float*)d_in[4];
    const float* pl0b = (const float*)d_in[5];
    const float* pnw  = (const float*)d_in[6];
    const float* pnb  = (const float*)d_in[7];
    const float* lng  = (const float*)d_in[8];
    const float* lnb  = (const float*)d_in[9];
    const float* f1w  = (const float*)d_in[10];
    const float* f1b  = (const float*)d_in[11];
    const float* f2w  = (const float*)d_in[12];
    const float* f2b  = (const float*)d_in[13];
    const int*   pidx = (const int*)d_in[14];
    const int*   esrc = (const int*)d_in[15];
    const int*   edst = (const int*)d_in[16];
    float* out = (float*)d_out;

    const int smem_bytes = (64 * 129 + 64 * 184 + 16384) * 4;   // 145664
    cudaFuncSetAttribute(e3_main_kernel,
                         cudaFuncAttributeMaxDynamicSharedMemorySize, smem_bytes);

    prep_kernel<<<452, 256>>>(node, pl0w, pl0b, l1);
    e3_main_kernel<<<NE / 64, 256, smem_bytes>>>(pair, pidx, esh, esrc, edst,
                                                 lng, lnb, f1w, f1b, f2w, f2b);
    finalize_kernel<<<NNODE, 256>>>(node, l1, pnw, pnb, out);
}

// round 6
// speedup vs baseline: 2.9386x; 2.9386x over previous
#include <cuda_runtime.h>
#include <cuda_bf16.h>
#include <cstdint>

#define B_     4
#define L_     256
#define NNODE  1024
#define DNODE  256
#define DPAIR  128
#define NE     65536
#define M0_    32
#define DIRR   56
#define WNUM_  1664

#define PW0   0.15811388300841897f
#define PW1   0.25f
#define S3C   0.5773502691896258f
#define F121  0.5477225575051661f

// device scratch (no allocations allowed)
__device__ float g_feats[NNODE * DIRR];
__device__ float g_sums [NNODE * DIRR];
__device__ float g_cnt  [NNODE];
// pre-split weights, bf16 hi/lo, already in padded smem layout
__device__ uint4 g_w1[4352];     // [hi 128x136][lo 128x136] bf16 = 69,632 B
__device__ uint4 g_w2[59904];    // [26 chunks][hi 128x72][lo 128x72] bf16 = 958,464 B

// ---------------- plain-PTX helpers (sm_80-level, safe on sm_103) ----------
__device__ __forceinline__ uint32_t smem_u32(const void* p) {
    uint32_t a;
    asm("{ .reg .u64 t; cvta.to.shared.u64 t, %1; cvt.u32.u64 %0, t; }"
        : "=r"(a) : "l"(p));
    return a;
}
__device__ __forceinline__ void ldsm_x4(uint32_t* r, uint32_t addr) {
    asm volatile("ldmatrix.sync.aligned.m8n8.x4.shared.b16 {%0,%1,%2,%3}, [%4];"
        : "=r"(r[0]), "=r"(r[1]), "=r"(r[2]), "=r"(r[3]) : "r"(addr));
}
__device__ __forceinline__ void ldsm_x4t(uint32_t* r, uint32_t addr) {
    asm volatile("ldmatrix.sync.aligned.m8n8.x4.trans.shared.b16 {%0,%1,%2,%3}, [%4];"
        : "=r"(r[0]), "=r"(r[1]), "=r"(r[2]), "=r"(r[3]) : "r"(addr));
}
__device__ __forceinline__ void mma_bf16(float* d, const uint32_t* a,
                                         uint32_t b0, uint32_t b1) {
    asm volatile("mma.sync.aligned.m16n8k16.row.col.f32.bf16.bf16.f32 "
        "{%0,%1,%2,%3}, {%4,%5,%6,%7}, {%8,%9}, {%0,%1,%2,%3};"
        : "+f"(d[0]), "+f"(d[1]), "+f"(d[2]), "+f"(d[3])
        : "r"(a[0]), "r"(a[1]), "r"(a[2]), "r"(a[3]), "r"(b0), "r"(b1));
}
__device__ __forceinline__ void cpasync16(uint32_t s, const void* g) {
    asm volatile("cp.async.cg.shared.global [%0], [%1], 16;" :: "r"(s), "l"(g));
}
#define CP_COMMIT() asm volatile("cp.async.commit_group;" ::: "memory")
#define CP_WAIT(N)  asm volatile("cp.async.wait_group %0;" :: "n"(N) : "memory")

// smem layout (bytes) -- 64 edges per CTA
#define SM_A     0        // 64x184 f32 A-coeffs (x staging 64x128 f32 first) = 47104
#define SM_HHI   47104    // 64x136 bf16 = 17408
#define SM_HLO   64512    // 17408
#define SM_W     81920    // W buffers: fc1 hi+lo 69632, or fc2 2x(hi 18432 + lo 18432)
#define SM_F2B   155648   // 1664 f32 = 6656
#define SM_F1B   162304   // 128 f32 = 512
#define SM_TOTAL 162816

// ---------------------------------------------------------------------------
__global__ void prep_zero_kernel() {
    int i = blockIdx.x * 1024 + threadIdx.x;
    if (i < NNODE * DIRR) g_sums[i] = 0.f;
    else if (i < NNODE * DIRR + NNODE) g_cnt[i - NNODE * DIRR] = 0.f;
}

__global__ __launch_bounds__(256) void prep_proj_kernel(
        const float* __restrict__ node, const float* __restrict__ w,
        const float* __restrict__ b,    const float* __restrict__ l1) {
    __shared__ float sw[DNODE * M0_];
    __shared__ float sx[16 * DNODE];
    int tid = threadIdx.x, n0 = blockIdx.x * 16;
    for (int i = tid; i < DNODE * M0_; i += 256) sw[i] = w[i];
    for (int i = tid; i < 16 * DNODE; i += 256) sx[i] = node[n0 * DNODE + i];
    __syncthreads();
    int warp = tid >> 5, lane = tid & 31;
    for (int r = 0; r < 2; ++r) {
        int nl = warp * 2 + r;
        float acc = b[lane];
        const float* x = sx + nl * DNODE;
#pragma unroll 8
        for (int k = 0; k < DNODE; ++k) acc += x[k] * sw[k * M0_ + lane];
        g_feats[(n0 + nl) * DIRR + lane] = acc;
    }
    for (int i = tid; i < 16 * 24; i += 256) {
        int nl = i / 24, m = i - nl * 24;
        g_feats[(n0 + nl) * DIRR + M0_ + m] = l1[(n0 + nl) * 24 + m];
    }
}

// split fc1_w and fc2_w into bf16 hi/lo in final padded layouts
__global__ void prep_wsplit_kernel(const float* __restrict__ f1w,
                                   const float* __restrict__ f2w) {
    int i = blockIdx.x * 256 + threadIdx.x;
    if (i < 128 * 136) {
        int k = i / 136, n = i - k * 136;
        float v = (n < 128) ? f1w[k * 128 + n] : 0.f;
        __nv_bfloat16 h = __float2bfloat16(v);
        __nv_bfloat16 l = __float2bfloat16(v - __bfloat162float(h));
        ((__nv_bfloat16*)g_w1)[i] = h;
        ((__nv_bfloat16*)g_w1)[128 * 136 + i] = l;
    } else {
        int j = i - 128 * 136;
        if (j < 26 * 128 * 72) {
            int c = j / (128 * 72), r = j - c * (128 * 72);
            int k = r / 72, n = r - k * 72;
            float v = (n < 64) ? f2w[k * WNUM_ + c * 64 + n] : 0.f;
            __nv_bfloat16 h = __float2bfloat16(v);
            __nv_bfloat16 l = __float2bfloat16(v - __bfloat162float(h));
            __nv_bfloat16* w2 = (__nv_bfloat16*)g_w2;
            w2[(size_t)c * 2 * 128 * 72 + (size_t)k * 72 + n] = h;
            w2[(size_t)c * 2 * 128 * 72 + 128 * 72 + (size_t)k * 72 + n] = l;
        }
    }
}

// ---------------------------------------------------------------------------
__launch_bounds__(256, 1) __global__
void e3_main_kernel(const float* __restrict__ pair,
                    const int*   __restrict__ pidx,
                    const float* __restrict__ esh,
                    const int*   __restrict__ esrc,
                    const int*   __restrict__ edst,
                    const float* __restrict__ lng,
                    const float* __restrict__ lnb,
                    const float* __restrict__ f1b,
                    const float* __restrict__ f2b) {
    extern __shared__ char smem[];
    float* sA     = (float*)(smem + SM_A);
    float* f2b_s  = (float*)(smem + SM_F2B);
    float* f1b_s  = (float*)(smem + SM_F1B);
    const uint32_t smW   = smem_u32(smem + SM_W);
    const uint32_t smHHI = smem_u32(smem + SM_HHI);
    const uint32_t smHLO = smem_u32(smem + SM_HLO);

    const int tid = threadIdx.x, warp = tid >> 5, lane = tid & 31;
    const int eb0 = blockIdx.x * 64;
    const int warp_m = warp & 3, warp_n = warp >> 2;
    const int gr = lane >> 2, tig = lane & 3;
    const int e0l = warp_m * 16 + gr, e1l = e0l + 8;

    // ---- issue cp.async for fc1 weights (group 0) --------------------------
#pragma unroll
    for (int u = 0; u < 17; ++u)
        cpasync16(smW + (tid + u * 256) * 16, (const char*)g_w1 + (tid + u * 256) * 16);
    CP_COMMIT();

    // ---- gather x into sA [64][128] f32; copy biases -----------------------
    for (int idx4 = tid; idx4 < 64 * 32; idx4 += 256) {
        int el = idx4 >> 5, c4 = idx4 & 31;
        int e = eb0 + el;
        int b = pidx[e], i = pidx[NE + e], j = pidx[2 * NE + e];
        ((float4*)sA)[el * 32 + c4] =
            ((const float4*)(pair + (size_t)(((b * L_) + i) * L_ + j) * DPAIR))[c4];
    }
    for (int i = tid; i < WNUM_; i += 256) f2b_s[i] = f2b[i];
    if (tid < 128) f1b_s[tid] = f1b[tid];
    __syncthreads();

    // ---- LayerNorm; write split x directly to hHi/hLo ----------------------
    {
        float g0 = lng[lane], g1 = lng[lane + 32], g2 = lng[lane + 64], g3 = lng[lane + 96];
        float b0 = lnb[lane], b1 = lnb[lane + 32], b2 = lnb[lane + 64], b3 = lnb[lane + 96];
        for (int ee = 0; ee < 8; ++ee) {
            int el = warp * 8 + ee;
            const float* xr = sA + el * 128;
            float x0 = xr[lane], x1 = xr[lane + 32], x2 = xr[lane + 64], x3 = xr[lane + 96];
            float s = x0 + x1 + x2 + x3;
#pragma unroll
            for (int o = 16; o > 0; o >>= 1) s += __shfl_xor_sync(0xffffffffu, s, o);
            float mu = s * (1.f / 128.f);
            float d0 = x0 - mu, d1 = x1 - mu, d2 = x2 - mu, d3 = x3 - mu;
            float q = d0 * d0 + d1 * d1 + d2 * d2 + d3 * d3;
#pragma unroll
            for (int o = 16; o > 0; o >>= 1) q += __shfl_xor_sync(0xffffffffu, q, o);
            float rstd = rsqrtf(q * (1.f / 128.f) + 1e-5f);
            float v[4] = {d0 * rstd * g0 + b0, d1 * rstd * g1 + b1,
                          d2 * rstd * g2 + b2, d3 * rstd * g3 + b3};
#pragma unroll
            for (int p = 0; p < 4; ++p) {
                int col = lane + p * 32;
                __nv_bfloat16 h = __float2bfloat16(v[p]);
                __nv_bfloat16 l = __float2bfloat16(v[p] - __bfloat162float(h));
                *(__nv_bfloat16*)(smem + SM_HHI + el * 272 + col * 2) = h;
                *(__nv_bfloat16*)(smem + SM_HLO + el * 272 + col * 2) = l;
            }
        }
    }
    __syncthreads();

    // ---- A-operand fragment preload (x) ------------------------------------
    uint32_t xh[8][4], xl[8][4];
    {
        int rowsel = warp_m * 16 + (lane & 15);
        uint32_t cextra = (lane & 16) ? 16 : 0;   // +8 cols * 2B
#pragma unroll
        for (int ks = 0; ks < 8; ++ks) {
            uint32_t off = rowsel * 272 + ks * 32 + cextra;
            ldsm_x4(xh[ks], smHHI + off);
            ldsm_x4(xl[ks], smHLO + off);
        }
    }
    CP_WAIT(0);
    __syncthreads();

    // ---- fc1 MMA: h[64,128] = relu(x @ fc1_w + b), 3-pass bf16 -------------
    float acc1[8][4];
#pragma unroll
    for (int t = 0; t < 8; ++t)
#pragma unroll
        for (int q = 0; q < 4; ++q) acc1[t][q] = 0.f;
    {
        const uint32_t w1hi = smW, w1lo = smW + 34816;
#pragma unroll
        for (int kp = 0; kp < 4; ++kp) {
            uint32_t rowoff = (kp * 32 + lane) * 272;
#pragma unroll
            for (int t = 0; t < 8; ++t) {
                uint32_t col2 = (warp_n * 64 + t * 8) * 2;
                uint32_t b4[4];
                ldsm_x4t(b4, w1hi + rowoff + col2);
                mma_bf16(acc1[t], xh[2 * kp],     b4[0], b4[1]);
                mma_bf16(acc1[t], xh[2 * kp + 1], b4[2], b4[3]);
                mma_bf16(acc1[t], xl[2 * kp],     b4[0], b4[1]);
                mma_bf16(acc1[t], xl[2 * kp + 1], b4[2], b4[3]);
                ldsm_x4t(b4, w1lo + rowoff + col2);
                mma_bf16(acc1[t], xh[2 * kp],     b4[0], b4[1]);
                mma_bf16(acc1[t], xh[2 * kp + 1], b4[2], b4[3]);
            }
        }
    }
    __syncthreads();   // all warps done reading w1 buffer

    // ---- issue cp.async for fc2 chunks 0 and 1 -----------------------------
    {
        const char* g0 = (const char*)g_w2;
#pragma unroll
        for (int u = 0; u < 9; ++u)
            cpasync16(smW + (tid + u * 256) * 16, g0 + (tid + u * 256) * 16);
        CP_COMMIT();
        const char* g1 = (const char*)g_w2 + 36864;
#pragma unroll
        for (int u = 0; u < 9; ++u)
            cpasync16(smW + 36864 + (tid + u * 256) * 16, g1 + (tid + u * 256) * 16);
        CP_COMMIT();
    }

    // ---- fc1 epilogue: bias+relu, split, store h ---------------------------
#pragma unroll
    for (int t = 0; t < 8; ++t) {
#pragma unroll
        for (int e = 0; e < 2; ++e) {
            int row = warp_m * 16 + gr + e * 8;
            int col = warp_n * 64 + t * 8 + 2 * tig;
            float v0 = fmaxf(acc1[t][2 * e]     + f1b_s[col],     0.f);
            float v1 = fmaxf(acc1[t][2 * e + 1] + f1b_s[col + 1], 0.f);
            __nv_bfloat16 h0 = __float2bfloat16(v0), h1 = __float2bfloat16(v1);
            float l0 = v0 - __bfloat162float(h0), l1 = v1 - __bfloat162float(h1);
            uint32_t off = row * 272 + col * 2;
            *(__nv_bfloat162*)(smem + SM_HHI + off) = __halves2bfloat162(h0, h1);
            *(__nv_bfloat162*)(smem + SM_HLO + off) =
                __halves2bfloat162(__float2bfloat16(l0), __float2bfloat16(l1));
        }
    }

    // ---- A coefficients (x in sA dead; write pitch 184) --------------------
    for (int idx = tid; idx < 64 * 184; idx += 256) {
        int el = idx / 184, a = idx - el * 184;
        int e = eb0 + el;
        const float* F  = g_feats + edst[e] * DIRR;
        const float* SH = esh + e * 9;
        float val;
        if (a < 32) {
            val = PW0 * F[a] * SH[0];
        } else if (a < 40) {
            int u = a - 32;
            val = (PW0 * S3C) * (F[32 + u * 3] * SH[1] + F[33 + u * 3] * SH[2]
                                 + F[34 + u * 3] * SH[3]);
        } else if (a < 136) {
            int t = a - 40; int u = t / 3, m = t - u * 3;
            val = (PW1 * S3C) * F[u] * SH[1 + m];
        } else if (a < 160) {
            int t = a - 136; int u = t / 3, m = t - u * 3;
            val = (PW1 * S3C) * F[32 + u * 3 + m] * SH[0];
        } else {
            int t = a - 160; int u = t / 3, m = t - u * 3;
            float xx = F[32 + u * 3], xy = F[33 + u * 3], xz = F[34 + u * 3];
            float s0 = SH[4], s1 = SH[5], s2 = SH[6], s3v = SH[7], s4 = SH[8];
            float t5;
            if (m == 0)      t5 = (xz * s0 + xy * s1 - xx * s4) * S3C - xx * s2 * (1.f / 3.f);
            else if (m == 1) t5 = (xx * s1 + xz * s3v) * S3C + xy * s2 * (2.f / 3.f);
            else             t5 = (xx * s0 + xy * s3v + xz * s4) * S3C - xz * s2 * (1.f / 3.f);
            val = (PW1 * F121) * t5;
        }
        sA[el * 184 + a] = val;
    }
    __syncthreads();   // h + A complete

    // ---- reload A-operand fragments (now h) ---------------------------------
    {
        int rowsel = warp_m * 16 + (lane & 15);
        uint32_t cextra = (lane & 16) ? 16 : 0;
#pragma unroll
        for (int ks = 0; ks < 8; ++ks) {
            uint32_t off = rowsel * 272 + ks * 32 + cextra;
            ldsm_x4(xh[ks], smHHI + off);
            ldsm_x4(xl[ks], smHLO + off);
        }
    }

    // ---- fc2 chunk loop fused with TP contraction ---------------------------
    float conv0[16], conv1[12];
#pragma unroll
    for (int o = 0; o < 16; ++o) conv0[o] = 0.f;
#pragma unroll
    for (int o = 0; o < 12; ++o) conv1[o] = 0.f;

    for (int c = 0; c < 26; ++c) {
        if (c < 25) CP_WAIT(1); else CP_WAIT(0);
        __syncthreads();

        float acc[4][4];
#pragma unroll
        for (int t = 0; t < 4; ++t)
#pragma unroll
            for (int q = 0; q < 4; ++q) acc[t][q] = 0.f;

        const uint32_t bhi = smW + (uint32_t)((c & 1) * 36864);
        const uint32_t blo = bhi + 18432;
#pragma unroll
        for (int kp = 0; kp < 4; ++kp) {
            uint32_t rowoff = (kp * 32 + lane) * 144;
#pragma unroll
            for (int t = 0; t < 4; ++t) {
                uint32_t col2 = (warp_n * 32 + t * 8) * 2;
                uint32_t b4[4];
                ldsm_x4t(b4, bhi + rowoff + col2);
                mma_bf16(acc[t], xh[2 * kp],     b4[0], b4[1]);
                mma_bf16(acc[t], xh[2 * kp + 1], b4[2], b4[3]);
                mma_bf16(acc[t], xl[2 * kp],     b4[0], b4[1]);
                mma_bf16(acc[t], xl[2 * kp + 1], b4[2], b4[3]);
                ldsm_x4t(b4, blo + rowoff + col2);
                mma_bf16(acc[t], xh[2 * kp],     b4[0], b4[1]);
                mma_bf16(acc[t], xh[2 * kp + 1], b4[2], b4[3]);
            }
        }

        // bias + contraction
        const float* f2bs = f2b_s + c * 64 + warp_n * 32;
        if (c < 16 || (c >= 21 && c < 25)) {
            int aoff = (c < 16) ? (c * 2 + warp_n) : (32 + (c - 21) * 2 + warp_n);
            float aA0 = sA[e0l * 184 + aoff];
            float aA1 = sA[e1l * 184 + aoff];
#pragma unroll
            for (int t = 0; t < 4; ++t) {
#pragma unroll
                for (int j = 0; j < 2; ++j) {
                    float bias = f2bs[t * 8 + 2 * tig + j];
                    conv0[t * 2 + j]     += aA0 * (acc[t][j]     + bias);
                    conv0[8 + t * 2 + j] += aA1 * (acc[t][2 + j] + bias);
                }
            }
        } else {
            int base = (c == 20) ? 136 : ((c == 25) ? 160 : 40);
            int uoff = (c < 20) ? (c - 16) * 8 : 0;
#pragma unroll
            for (int t = 0; t < 4; ++t) {
                int u = uoff + warp_n * 4 + t;
                const float* A0 = sA + e0l * 184 + base + u * 3;
                const float* A1 = sA + e1l * 184 + base + u * 3;
#pragma unroll
                for (int j = 0; j < 2; ++j) {
                    float bias = f2bs[t * 8 + 2 * tig + j];
                    float p0 = acc[t][j] + bias, p1 = acc[t][2 + j] + bias;
#pragma unroll
                    for (int m = 0; m < 3; ++m) {
                        conv1[j * 3 + m]     += A0[m] * p0;
                        conv1[6 + j * 3 + m] += A1[m] * p1;
                    }
                }
            }
        }

        __syncthreads();   // all warps done reading buf[c&1]
        if (c + 2 < 26) {
            const char* gsrc = (const char*)g_w2 + (size_t)(c + 2) * 36864;
            uint32_t sdst = smW + (uint32_t)((c & 1) * 36864);
#pragma unroll
            for (int u = 0; u < 9; ++u)
                cpasync16(sdst + (tid + u * 256) * 16, gsrc + (tid + u * 256) * 16);
            CP_COMMIT();
        }
    }

    // ---- epilogue: scatter-add ----------------------------------------------
    {
        int s0 = esrc[eb0 + e0l] * DIRR;
        int s1 = esrc[eb0 + e1l] * DIRR;
#pragma unroll
        for (int t = 0; t < 4; ++t)
#pragma unroll
            for (int j = 0; j < 2; ++j) {
                int v = t * 8 + 2 * tig + j;
                atomicAdd(&g_sums[s0 + v], conv0[t * 2 + j]);
                atomicAdd(&g_sums[s1 + v], conv0[8 + t * 2 + j]);
            }
#pragma unroll
        for (int j = 0; j < 2; ++j)
#pragma unroll
            for (int m = 0; m < 3; ++m) {
                int o = 32 + (2 * tig + j) * 3 + m;
                atomicAdd(&g_sums[s0 + o], conv1[j * 3 + m]);
                atomicAdd(&g_sums[s1 + o], conv1[6 + j * 3 + m]);
            }
    }
    if (tid < 64) atomicAdd(&g_cnt[esrc[eb0 + tid]], 1.f);
}

// ---------------------------------------------------------------------------
__global__ void finalize_kernel(const float* __restrict__ node,
                                const float* __restrict__ l1,
                                const float* __restrict__ pnw,
                                const float* __restrict__ pnb,
                                float* __restrict__ out) {
    int n = blockIdx.x;
    __shared__ float o0[32];
    float inv = 1.f / fmaxf(g_cnt[n], 1.f);
    if (threadIdx.x < 32) o0[threadIdx.x] = g_sums[n * DIRR + threadIdx.x] * inv;
    __syncthreads();
    int d = threadIdx.x;
    float acc = pnb[d];
#pragma unroll
    for (int u = 0; u < 32; ++u) acc += o0[u] * pnw[u * DNODE + d];
    out[n * DNODE + d] = acc + node[n * DNODE + d];
    if (d < 24)
        out[NNODE * DNODE + n * 24 + d] = g_sums[n * DIRR + 32 + d] * inv + l1[n * 24 + d];
}

// ---------------------------------------------------------------------------
extern "C" void kernel_launch(void* const* d_in, const int* in_sizes, int n_in,
                              void* d_out, int out_size) {
    const float* node = (const float*)d_in[0];
    const float* pair = (const float*)d_in[1];
    const float* l1   = (const float*)d_in[2];
    const float* esh  = (const float*)d_in[3];
    const float* pl0w = (const float*)d_in[4];
    const float* pl0b = (const float*)d_in[5];
    const float* pnw  = (const float*)d_in[6];
    const float* pnb  = (const float*)d_in[7];
    const float* lng  = (const float*)d_in[8];
    const float* lnb  = (const float*)d_in[9];
    const float* f1w  = (const float*)d_in[10];
    const float* f1b  = (const float*)d_in[11];
    const float* f2w  = (const float*)d_in[12];
    const float* f2b  = (const float*)d_in[13];
    const int*   pidx = (const int*)d_in[14];
    const int*   esrc = (const int*)d_in[15];
    const int*   edst = (const int*)d_in[16];
    float* out = (float*)d_out;

    cudaFuncSetAttribute(e3_main_kernel,
                         cudaFuncAttributeMaxDynamicSharedMemorySize, SM_TOTAL);

    prep_zero_kernel<<<57, 1024>>>();
    prep_proj_kernel<<<64, 256>>>(node, pl0w, pl0b, l1);
    prep_wsplit_kernel<<<1004, 256>>>(f1w, f2w);
    e3_main_kernel<<<NE / 64, 256, SM_TOTAL>>>(pair, pidx, esh, esrc, edst,
                                               lng, lnb, f1b, f2b);
    finalize_kernel<<<NNODE, 256>>>(node, l1, pnw, pnb, out);
}

// round 7
// speedup vs baseline: 3.3583x; 1.1428x over previous
#include <cuda_runtime.h>
#include <cuda_bf16.h>
#include <cstdint>

#define B_     4
#define L_     256
#define NNODE  1024
#define DNODE  256
#define DPAIR  128
#define NE     65536
#define M0_    32
#define DIRR   56
#define WNUM_  1664

#define PW0   0.15811388300841897f
#define PW1   0.25f
#define S3C   0.5773502691896258f
#define F121  0.5477225575051661f

// device scratch (no allocations allowed)
__device__ float g_feats[NNODE * DIRR];
__device__ float g_sums [NNODE * DIRR];
__device__ float g_cnt  [NNODE];
// pre-split weights, bf16 hi/lo, already in padded smem layout
__device__ uint4 g_w1[4352];     // [hi 128x136][lo 128x136] bf16 = 69,632 B
__device__ uint4 g_w2[59904];    // [26 chunks][hi 128x72][lo 128x72] bf16 = 958,464 B

// ---------------- plain-PTX helpers (sm_80-level, safe on sm_103) ----------
__device__ __forceinline__ uint32_t smem_u32(const void* p) {
    uint32_t a;
    asm("{ .reg .u64 t; cvta.to.shared.u64 t, %1; cvt.u32.u64 %0, t; }"
        : "=r"(a) : "l"(p));
    return a;
}
__device__ __forceinline__ void ldsm_x4(uint32_t* r, uint32_t addr) {
    asm volatile("ldmatrix.sync.aligned.m8n8.x4.shared.b16 {%0,%1,%2,%3}, [%4];"
        : "=r"(r[0]), "=r"(r[1]), "=r"(r[2]), "=r"(r[3]) : "r"(addr));
}
__device__ __forceinline__ void ldsm_x4t(uint32_t* r, uint32_t addr) {
    asm volatile("ldmatrix.sync.aligned.m8n8.x4.trans.shared.b16 {%0,%1,%2,%3}, [%4];"
        : "=r"(r[0]), "=r"(r[1]), "=r"(r[2]), "=r"(r[3]) : "r"(addr));
}
__device__ __forceinline__ void mma_bf16(float* d, const uint32_t* a,
                                         uint32_t b0, uint32_t b1) {
    asm volatile("mma.sync.aligned.m16n8k16.row.col.f32.bf16.bf16.f32 "
        "{%0,%1,%2,%3}, {%4,%5,%6,%7}, {%8,%9}, {%0,%1,%2,%3};"
        : "+f"(d[0]), "+f"(d[1]), "+f"(d[2]), "+f"(d[3])
        : "r"(a[0]), "r"(a[1]), "r"(a[2]), "r"(a[3]), "r"(b0), "r"(b1));
}
__device__ __forceinline__ void cpasync16(uint32_t s, const void* g) {
    asm volatile("cp.async.cg.shared.global [%0], [%1], 16;" :: "r"(s), "l"(g));
}
#define CP_COMMIT() asm volatile("cp.async.commit_group;" ::: "memory")
#define CP_WAIT(N)  asm volatile("cp.async.wait_group %0;" :: "n"(N) : "memory")

// smem layout (bytes) -- 64 edges per CTA
#define SM_A     0        // 64x184 f32 A-coeffs (x staging 64x128 f32 first) = 47104
#define SM_HHI   47104    // 64x136 bf16 = 17408
#define SM_HLO   64512    // 17408
#define SM_W     81920    // W buffers: fc1 hi+lo 69632, or fc2 2x(hi 18432 + lo 18432)
#define SM_F2B   155648   // 1664 f32 = 6656
#define SM_F1B   162304   // 128 f32 = 512
#define SM_TOTAL 162816

#define THREADS  512

// ---------------------------------------------------------------------------
__global__ void prep_zero_kernel() {
    int i = blockIdx.x * 1024 + threadIdx.x;
    if (i < NNODE * DIRR) g_sums[i] = 0.f;
    else if (i < NNODE * DIRR + NNODE) g_cnt[i - NNODE * DIRR] = 0.f;
}

__global__ __launch_bounds__(256) void prep_proj_kernel(
        const float* __restrict__ node, const float* __restrict__ w,
        const float* __restrict__ b,    const float* __restrict__ l1) {
    __shared__ float sw[DNODE * M0_];
    __shared__ float sx[16 * DNODE];
    int tid = threadIdx.x, n0 = blockIdx.x * 16;
    for (int i = tid; i < DNODE * M0_; i += 256) sw[i] = w[i];
    for (int i = tid; i < 16 * DNODE; i += 256) sx[i] = node[n0 * DNODE + i];
    __syncthreads();
    int warp = tid >> 5, lane = tid & 31;
    for (int r = 0; r < 2; ++r) {
        int nl = warp * 2 + r;
        float acc = b[lane];
        const float* x = sx + nl * DNODE;
#pragma unroll 8
        for (int k = 0; k < DNODE; ++k) acc += x[k] * sw[k * M0_ + lane];
        g_feats[(n0 + nl) * DIRR + lane] = acc;
    }
    for (int i = tid; i < 16 * 24; i += 256) {
        int nl = i / 24, m = i - nl * 24;
        g_feats[(n0 + nl) * DIRR + M0_ + m] = l1[(n0 + nl) * 24 + m];
    }
}

// split fc1_w and fc2_w into bf16 hi/lo in final padded layouts
__global__ void prep_wsplit_kernel(const float* __restrict__ f1w,
                                   const float* __restrict__ f2w) {
    int i = blockIdx.x * 256 + threadIdx.x;
    if (i < 128 * 136) {
        int k = i / 136, n = i - k * 136;
        float v = (n < 128) ? f1w[k * 128 + n] : 0.f;
        __nv_bfloat16 h = __float2bfloat16(v);
        __nv_bfloat16 l = __float2bfloat16(v - __bfloat162float(h));
        ((__nv_bfloat16*)g_w1)[i] = h;
        ((__nv_bfloat16*)g_w1)[128 * 136 + i] = l;
    } else {
        int j = i - 128 * 136;
        if (j < 26 * 128 * 72) {
            int c = j / (128 * 72), r = j - c * (128 * 72);
            int k = r / 72, n = r - k * 72;
            float v = (n < 64) ? f2w[k * WNUM_ + c * 64 + n] : 0.f;
            __nv_bfloat16 h = __float2bfloat16(v);
            __nv_bfloat16 l = __float2bfloat16(v - __bfloat162float(h));
            __nv_bfloat16* w2 = (__nv_bfloat16*)g_w2;
            w2[(size_t)c * 2 * 128 * 72 + (size_t)k * 72 + n] = h;
            w2[(size_t)c * 2 * 128 * 72 + 128 * 72 + (size_t)k * 72 + n] = l;
        }
    }
}

// ---------------------------------------------------------------------------
__launch_bounds__(THREADS, 1) __global__
void e3_main_kernel(const float* __restrict__ pair,
                    const int*   __restrict__ pidx,
                    const float* __restrict__ esh,
                    const int*   __restrict__ esrc,
                    const int*   __restrict__ edst,
                    const float* __restrict__ lng,
                    const float* __restrict__ lnb,
                    const float* __restrict__ f1b,
                    const float* __restrict__ f2b) {
    extern __shared__ char smem[];
    float* sA     = (float*)(smem + SM_A);
    float* f2b_s  = (float*)(smem + SM_F2B);
    float* f1b_s  = (float*)(smem + SM_F1B);
    const uint32_t smW   = smem_u32(smem + SM_W);
    const uint32_t smHHI = smem_u32(smem + SM_HHI);
    const uint32_t smHLO = smem_u32(smem + SM_HLO);

    const int tid = threadIdx.x, warp = tid >> 5, lane = tid & 31;
    const int eb0 = blockIdx.x * 64;
    const int warp_m = warp & 3, warp_n = warp >> 2;   // 4m x 4n
    const int gr = lane >> 2, tig = lane & 3;
    const int e0l = warp_m * 16 + gr, e1l = e0l + 8;

    // ---- issue cp.async for fc1 weights (group 0) --------------------------
#pragma unroll
    for (int u = 0; u < 9; ++u) {
        int idx = tid + u * THREADS;
        if (idx < 4352)
            cpasync16(smW + idx * 16, (const char*)g_w1 + idx * 16);
    }
    CP_COMMIT();

    // ---- gather x into sA [64][128] f32; copy biases -----------------------
    for (int idx4 = tid; idx4 < 64 * 32; idx4 += THREADS) {
        int el = idx4 >> 5, c4 = idx4 & 31;
        int e = eb0 + el;
        int b = pidx[e], i = pidx[NE + e], j = pidx[2 * NE + e];
        ((float4*)sA)[el * 32 + c4] =
            ((const float4*)(pair + (size_t)(((b * L_) + i) * L_ + j) * DPAIR))[c4];
    }
    for (int i = tid; i < WNUM_; i += THREADS) f2b_s[i] = f2b[i];
    if (tid < 128) f1b_s[tid] = f1b[tid];
    __syncthreads();

    // ---- LayerNorm; write split x directly to hHi/hLo (warp: 4 edges) ------
    {
        float g0 = lng[lane], g1 = lng[lane + 32], g2 = lng[lane + 64], g3 = lng[lane + 96];
        float b0 = lnb[lane], b1 = lnb[lane + 32], b2 = lnb[lane + 64], b3 = lnb[lane + 96];
        for (int ee = 0; ee < 4; ++ee) {
            int el = warp * 4 + ee;
            const float* xr = sA + el * 128;
            float x0 = xr[lane], x1 = xr[lane + 32], x2 = xr[lane + 64], x3 = xr[lane + 96];
            float s = x0 + x1 + x2 + x3;
#pragma unroll
            for (int o = 16; o > 0; o >>= 1) s += __shfl_xor_sync(0xffffffffu, s, o);
            float mu = s * (1.f / 128.f);
            float d0 = x0 - mu, d1 = x1 - mu, d2 = x2 - mu, d3 = x3 - mu;
            float q = d0 * d0 + d1 * d1 + d2 * d2 + d3 * d3;
#pragma unroll
            for (int o = 16; o > 0; o >>= 1) q += __shfl_xor_sync(0xffffffffu, q, o);
            float rstd = rsqrtf(q * (1.f / 128.f) + 1e-5f);
            float v[4] = {d0 * rstd * g0 + b0, d1 * rstd * g1 + b1,
                          d2 * rstd * g2 + b2, d3 * rstd * g3 + b3};
#pragma unroll
            for (int p = 0; p < 4; ++p) {
                int col = lane + p * 32;
                __nv_bfloat16 h = __float2bfloat16(v[p]);
                __nv_bfloat16 l = __float2bfloat16(v[p] - __bfloat162float(h));
                *(__nv_bfloat16*)(smem + SM_HHI + el * 272 + col * 2) = h;
                *(__nv_bfloat16*)(smem + SM_HLO + el * 272 + col * 2) = l;
            }
        }
    }
    __syncthreads();

    // ---- A-operand fragment preload (x) ------------------------------------
    uint32_t xh[8][4], xl[8][4];
    {
        int rowsel = warp_m * 16 + (lane & 15);
        uint32_t cextra = (lane & 16) ? 16 : 0;   // +8 cols * 2B
#pragma unroll
        for (int ks = 0; ks < 8; ++ks) {
            uint32_t off = rowsel * 272 + ks * 32 + cextra;
            ldsm_x4(xh[ks], smHHI + off);
            ldsm_x4(xl[ks], smHLO + off);
        }
    }
    CP_WAIT(0);
    __syncthreads();

    // ---- fc1 MMA: h[64,128] = relu(x @ fc1_w + b), 3-pass bf16 -------------
    // warp tile: 16 edges x 32 cols (warp_n covers 32-col band)
    float acc1[4][4];
#pragma unroll
    for (int t = 0; t < 4; ++t)
#pragma unroll
        for (int q = 0; q < 4; ++q) acc1[t][q] = 0.f;
    {
        const uint32_t w1hi = smW, w1lo = smW + 34816;
#pragma unroll
        for (int kp = 0; kp < 4; ++kp) {
            uint32_t rowoff = (kp * 32 + lane) * 272;
#pragma unroll
            for (int t = 0; t < 4; ++t) {
                uint32_t col2 = (warp_n * 32 + t * 8) * 2;
                uint32_t b4[4];
                ldsm_x4t(b4, w1hi + rowoff + col2);
                mma_bf16(acc1[t], xh[2 * kp],     b4[0], b4[1]);
                mma_bf16(acc1[t], xh[2 * kp + 1], b4[2], b4[3]);
                mma_bf16(acc1[t], xl[2 * kp],     b4[0], b4[1]);
                mma_bf16(acc1[t], xl[2 * kp + 1], b4[2], b4[3]);
                ldsm_x4t(b4, w1lo + rowoff + col2);
                mma_bf16(acc1[t], xh[2 * kp],     b4[0], b4[1]);
                mma_bf16(acc1[t], xh[2 * kp + 1], b4[2], b4[3]);
            }
        }
    }
    __syncthreads();   // all warps done reading w1 buffer

    // ---- issue cp.async for fc2 chunks 0 and 1 -----------------------------
    {
        const char* g0 = (const char*)g_w2;
#pragma unroll
        for (int u = 0; u < 5; ++u) {
            int idx = tid + u * THREADS;
            if (idx < 2304) cpasync16(smW + idx * 16, g0 + idx * 16);
        }
        CP_COMMIT();
        const char* g1 = (const char*)g_w2 + 36864;
#pragma unroll
        for (int u = 0; u < 5; ++u) {
            int idx = tid + u * THREADS;
            if (idx < 2304) cpasync16(smW + 36864 + idx * 16, g1 + idx * 16);
        }
        CP_COMMIT();
    }

    // ---- fc1 epilogue: bias+relu, split, store h ---------------------------
#pragma unroll
    for (int t = 0; t < 4; ++t) {
#pragma unroll
        for (int e = 0; e < 2; ++e) {
            int row = warp_m * 16 + gr + e * 8;
            int col = warp_n * 32 + t * 8 + 2 * tig;
            float v0 = fmaxf(acc1[t][2 * e]     + f1b_s[col],     0.f);
            float v1 = fmaxf(acc1[t][2 * e + 1] + f1b_s[col + 1], 0.f);
            __nv_bfloat16 h0 = __float2bfloat16(v0), h1 = __float2bfloat16(v1);
            float l0 = v0 - __bfloat162float(h0), l1 = v1 - __bfloat162float(h1);
            uint32_t off = row * 272 + col * 2;
            *(__nv_bfloat162*)(smem + SM_HHI + off) = __halves2bfloat162(h0, h1);
            *(__nv_bfloat162*)(smem + SM_HLO + off) =
                __halves2bfloat162(__float2bfloat16(l0), __float2bfloat16(l1));
        }
    }

    // ---- A coefficients (x in sA dead; write pitch 184) --------------------
    for (int idx = tid; idx < 64 * 184; idx += THREADS) {
        int el = idx / 184, a = idx - el * 184;
        int e = eb0 + el;
        const float* F  = g_feats + edst[e] * DIRR;
        const float* SH = esh + e * 9;
        float val;
        if (a < 32) {
            val = PW0 * F[a] * SH[0];
        } else if (a < 40) {
            int u = a - 32;
            val = (PW0 * S3C) * (F[32 + u * 3] * SH[1] + F[33 + u * 3] * SH[2]
                                 + F[34 + u * 3] * SH[3]);
        } else if (a < 136) {
            int t = a - 40; int u = t / 3, m = t - u * 3;
            val = (PW1 * S3C) * F[u] * SH[1 + m];
        } else if (a < 160) {
            int t = a - 136; int u = t / 3, m = t - u * 3;
            val = (PW1 * S3C) * F[32 + u * 3 + m] * SH[0];
        } else {
            int t = a - 160; int u = t / 3, m = t - u * 3;
            float xx = F[32 + u * 3], xy = F[33 + u * 3], xz = F[34 + u * 3];
            float s0 = SH[4], s1 = SH[5], s2 = SH[6], s3v = SH[7], s4 = SH[8];
            float t5;
            if (m == 0)      t5 = (xz * s0 + xy * s1 - xx * s4) * S3C - xx * s2 * (1.f / 3.f);
            else if (m == 1) t5 = (xx * s1 + xz * s3v) * S3C + xy * s2 * (2.f / 3.f);
            else             t5 = (xx * s0 + xy * s3v + xz * s4) * S3C - xz * s2 * (1.f / 3.f);
            val = (PW1 * F121) * t5;
        }
        sA[el * 184 + a] = val;
    }
    __syncthreads();   // h + A complete

    // ---- reload A-operand fragments (now h) ---------------------------------
    {
        int rowsel = warp_m * 16 + (lane & 15);
        uint32_t cextra = (lane & 16) ? 16 : 0;
#pragma unroll
        for (int ks = 0; ks < 8; ++ks) {
            uint32_t off = rowsel * 272 + ks * 32 + cextra;
            ldsm_x4(xh[ks], smHHI + off);
            ldsm_x4(xl[ks], smHLO + off);
        }
    }

    // ---- fc2 chunk loop fused with TP contraction ---------------------------
    // warp tile per chunk: 16 edges x 16 cols (warp_n covers 16-col band)
    float conv0[8], conv1[12];
#pragma unroll
    for (int o = 0; o < 8; ++o) conv0[o] = 0.f;
#pragma unroll
    for (int o = 0; o < 12; ++o) conv1[o] = 0.f;

    for (int c = 0; c < 26; ++c) {
        if (c < 25) CP_WAIT(1); else CP_WAIT(0);
        __syncthreads();

        float acc[2][4];
#pragma unroll
        for (int t = 0; t < 2; ++t)
#pragma unroll
            for (int q = 0; q < 4; ++q) acc[t][q] = 0.f;

        const uint32_t bhi = smW + (uint32_t)((c & 1) * 36864);
        const uint32_t blo = bhi + 18432;
#pragma unroll
        for (int kp = 0; kp < 4; ++kp) {
            uint32_t rowoff = (kp * 32 + lane) * 144;
#pragma unroll
            for (int t = 0; t < 2; ++t) {
                uint32_t col2 = (warp_n * 16 + t * 8) * 2;
                uint32_t b4[4];
                ldsm_x4t(b4, bhi + rowoff + col2);
                mma_bf16(acc[t], xh[2 * kp],     b4[0], b4[1]);
                mma_bf16(acc[t], xh[2 * kp + 1], b4[2], b4[3]);
                mma_bf16(acc[t], xl[2 * kp],     b4[0], b4[1]);
                mma_bf16(acc[t], xl[2 * kp + 1], b4[2], b4[3]);
                ldsm_x4t(b4, blo + rowoff + col2);
                mma_bf16(acc[t], xh[2 * kp],     b4[0], b4[1]);
                mma_bf16(acc[t], xh[2 * kp + 1], b4[2], b4[3]);
            }
        }

        // bias + contraction
        const float* f2bs = f2b_s + c * 64 + warp_n * 16;
        if (c < 16 || (c >= 21 && c < 25)) {
            int aoff = (c < 16) ? (c * 2 + (warp_n >> 1))
                                : (32 + (c - 21) * 2 + (warp_n >> 1));
            float aA0 = sA[e0l * 184 + aoff];
            float aA1 = sA[e1l * 184 + aoff];
#pragma unroll
            for (int t = 0; t < 2; ++t) {
#pragma unroll
                for (int j = 0; j < 2; ++j) {
                    float bias = f2bs[t * 8 + 2 * tig + j];
                    conv0[t * 2 + j]     += aA0 * (acc[t][j]     + bias);
                    conv0[4 + t * 2 + j] += aA1 * (acc[t][2 + j] + bias);
                }
            }
        } else {
            int base = (c == 20) ? 136 : ((c == 25) ? 160 : 40);
            int uoff = (c < 20) ? (c - 16) * 8 : 0;
#pragma unroll
            for (int t = 0; t < 2; ++t) {
                int u = uoff + warp_n * 2 + t;
                const float* A0 = sA + e0l * 184 + base + u * 3;
                const float* A1 = sA + e1l * 184 + base + u * 3;
#pragma unroll
                for (int j = 0; j < 2; ++j) {
                    float bias = f2bs[t * 8 + 2 * tig + j];
                    float p0 = acc[t][j] + bias, p1 = acc[t][2 + j] + bias;
#pragma unroll
                    for (int m = 0; m < 3; ++m) {
                        conv1[j * 3 + m]     += A0[m] * p0;
                        conv1[6 + j * 3 + m] += A1[m] * p1;
                    }
                }
            }
        }

        __syncthreads();   // all warps done reading buf[c&1]
        if (c + 2 < 26) {
            const char* gsrc = (const char*)g_w2 + (size_t)(c + 2) * 36864;
            uint32_t sdst = smW + (uint32_t)((c & 1) * 36864);
#pragma unroll
            for (int u = 0; u < 5; ++u) {
                int idx = tid + u * THREADS;
                if (idx < 2304) cpasync16(sdst + idx * 16, gsrc + idx * 16);
            }
            CP_COMMIT();
        }
    }

    // ---- epilogue: scatter-add ----------------------------------------------
    {
        int s0 = esrc[eb0 + e0l] * DIRR;
        int s1 = esrc[eb0 + e1l] * DIRR;
#pragma unroll
        for (int t = 0; t < 2; ++t)
#pragma unroll
            for (int j = 0; j < 2; ++j) {
                int v = (warp_n & 1) * 16 + t * 8 + 2 * tig + j;
                atomicAdd(&g_sums[s0 + v], conv0[t * 2 + j]);
                atomicAdd(&g_sums[s1 + v], conv0[4 + t * 2 + j]);
            }
#pragma unroll
        for (int j = 0; j < 2; ++j)
#pragma unroll
            for (int m = 0; m < 3; ++m) {
                int o = 32 + (2 * tig + j) * 3 + m;
                atomicAdd(&g_sums[s0 + o], conv1[j * 3 + m]);
                atomicAdd(&g_sums[s1 + o], conv1[6 + j * 3 + m]);
            }
    }
    if (tid < 64) atomicAdd(&g_cnt[esrc[eb0 + tid]], 1.f);
}

// ---------------------------------------------------------------------------
__global__ void finalize_kernel(const float* __restrict__ node,
                                const float* __restrict__ l1,
                                const float* __restrict__ pnw,
                                const float* __restrict__ pnb,
                                float* __restrict__ out) {
    int n = blockIdx.x;
    __shared__ float o0[32];
    float inv = 1.f / fmaxf(g_cnt[n], 1.f);
    if (threadIdx.x < 32) o0[threadIdx.x] = g_sums[n * DIRR + threadIdx.x] * inv;
    __syncthreads();
    int d = threadIdx.x;
    float acc = pnb[d];
#pragma unroll
    for (int u = 0; u < 32; ++u) acc += o0[u] * pnw[u * DNODE + d];
    out[n * DNODE + d] = acc + node[n * DNODE + d];
    if (d < 24)
        out[NNODE * DNODE + n * 24 + d] = g_sums[n * DIRR + 32 + d] * inv + l1[n * 24 + d];
}

// ---------------------------------------------------------------------------
extern "C" void kernel_launch(void* const* d_in, const int* in_sizes, int n_in,
                              void* d_out, int out_size) {
    const float* node = (const float*)d_in[0];
    const float* pair = (const float*)d_in[1];
    const float* l1   = (const float*)d_in[2];
    const float* esh  = (const float*)d_in[3];
    const float* pl0w = (const float*)d_in[4];
    const float* pl0b = (const float*)d_in[5];
    const float* pnw  = (const float*)d_in[6];
    const float* pnb  = (const float*)d_in[7];
    const float* lng  = (const float*)d_in[8];
    const float* lnb  = (const float*)d_in[9];
    const float* f1w  = (const float*)d_in[10];
    const float* f1b  = (const float*)d_in[11];
    const float* f2w  = (const float*)d_in[12];
    const float* f2b  = (const float*)d_in[13];
    const int*   pidx = (const int*)d_in[14];
    const int*   esrc = (const int*)d_in[15];
    const int*   edst = (const int*)d_in[16];
    float* out = (float*)d_out;

    cudaFuncSetAttribute(e3_main_kernel,
                         cudaFuncAttributeMaxDynamicSharedMemorySize, SM_TOTAL);

    prep_zero_kernel<<<57, 1024>>>();
    prep_proj_kernel<<<64, 256>>>(node, pl0w, pl0b, l1);
    prep_wsplit_kernel<<<1004, 256>>>(f1w, f2w);
    e3_main_kernel<<<NE / 64, THREADS, SM_TOTAL>>>(pair, pidx, esh, esrc, edst,
                                                   lng, lnb, f1b, f2b);
    finalize_kernel<<<NNODE, 256>>>(node, l1, pnw, pnb, out);
}

// round 8
// speedup vs baseline: 4.3375x; 1.2916x over previous
#include <cuda_runtime.h>
#include <cuda_fp16.h>
#include <cstdint>

#define B_     4
#define L_     256
#define NNODE  1024
#define DNODE  256
#define DPAIR  128
#define NE     65536
#define M0_    32
#define DIRR   56
#define WNUM_  1664

#define PW0   0.15811388300841897f
#define PW1   0.25f
#define S3C   0.5773502691896258f
#define F121  0.5477225575051661f

// device scratch (no allocations allowed)
__device__ float g_feats[NNODE * DIRR];
__device__ float g_sums [NNODE * DIRR];
__device__ float g_cnt  [NNODE];
// pre-split weights (fp16), padded + column-permuted layouts
__device__ uint4 g_w1[2176];     // fc1: 128 x 136 fp16 = 34,816 B
__device__ uint4 g_w2[28288];    // fc2: 13 chunks x 128 x 136 fp16 = 452,608 B

// ---------------- plain-PTX helpers (sm_80-level, safe on sm_103) ----------
__device__ __forceinline__ uint32_t smem_u32(const void* p) {
    uint32_t a;
    asm("{ .reg .u64 t; cvta.to.shared.u64 t, %1; cvt.u32.u64 %0, t; }"
        : "=r"(a) : "l"(p));
    return a;
}
__device__ __forceinline__ void ldsm_x4(uint32_t* r, uint32_t addr) {
    asm volatile("ldmatrix.sync.aligned.m8n8.x4.shared.b16 {%0,%1,%2,%3}, [%4];"
        : "=r"(r[0]), "=r"(r[1]), "=r"(r[2]), "=r"(r[3]) : "r"(addr));
}
__device__ __forceinline__ void ldsm_x4t(uint32_t* r, uint32_t addr) {
    asm volatile("ldmatrix.sync.aligned.m8n8.x4.trans.shared.b16 {%0,%1,%2,%3}, [%4];"
        : "=r"(r[0]), "=r"(r[1]), "=r"(r[2]), "=r"(r[3]) : "r"(addr));
}
__device__ __forceinline__ void mma_f16(float* d, const uint32_t* a,
                                        uint32_t b0, uint32_t b1) {
    asm volatile("mma.sync.aligned.m16n8k16.row.col.f32.f16.f16.f32 "
        "{%0,%1,%2,%3}, {%4,%5,%6,%7}, {%8,%9}, {%0,%1,%2,%3};"
        : "+f"(d[0]), "+f"(d[1]), "+f"(d[2]), "+f"(d[3])
        : "r"(a[0]), "r"(a[1]), "r"(a[2]), "r"(a[3]), "r"(b0), "r"(b1));
}
__device__ __forceinline__ void cpasync16(uint32_t s, const void* g) {
    asm volatile("cp.async.cg.shared.global [%0], [%1], 16;" :: "r"(s), "l"(g));
}
#define CP_COMMIT() asm volatile("cp.async.commit_group;" ::: "memory")
#define CP_WAIT(N)  asm volatile("cp.async.wait_group %0;" :: "n"(N) : "memory")

// smem layout (bytes) -- 64 edges per CTA
#define SM_A     0        // 64x184 f32 A-coeffs (x staging 64x128 f32 first) = 47104
#define SM_HHI   47104    // 64x136 fp16 = 17408 (pitch 272 B)
#define SM_HLO   64512    // 17408
#define SM_W     81920    // 3 x 34816 = 104448 (slot0 doubles as fc1 buffer)
#define SM_F2B   186368   // 1664 f32 = 6656
#define SM_F1B   193024   // 128 f32 = 512
#define SM_TOTAL 193536

#define THREADS  512
#define CHUNK_B  34816    // one fc2 chunk: 128 rows x 136 fp16 cols

// ---------------------------------------------------------------------------
__global__ void prep_zero_kernel() {
    int i = blockIdx.x * 1024 + threadIdx.x;
    if (i < NNODE * DIRR) g_sums[i] = 0.f;
    else if (i < NNODE * DIRR + NNODE) g_cnt[i - NNODE * DIRR] = 0.f;
}

__global__ __launch_bounds__(256) void prep_proj_kernel(
        const float* __restrict__ node, const float* __restrict__ w,
        const float* __restrict__ b,    const float* __restrict__ l1) {
    __shared__ float sw[DNODE * M0_];
    __shared__ float sx[16 * DNODE];
    int tid = threadIdx.x, n0 = blockIdx.x * 16;
    for (int i = tid; i < DNODE * M0_; i += 256) sw[i] = w[i];
    for (int i = tid; i < 16 * DNODE; i += 256) sx[i] = node[n0 * DNODE + i];
    __syncthreads();
    int warp = tid >> 5, lane = tid & 31;
    for (int r = 0; r < 2; ++r) {
        int nl = warp * 2 + r;
        float acc = b[lane];
        const float* x = sx + nl * DNODE;
#pragma unroll 8
        for (int k = 0; k < DNODE; ++k) acc += x[k] * sw[k * M0_ + lane];
        g_feats[(n0 + nl) * DIRR + lane] = acc;
    }
    for (int i = tid; i < 16 * 24; i += 256) {
        int nl = i / 24, m = i - nl * 24;
        g_feats[(n0 + nl) * DIRR + M0_ + m] = l1[(n0 + nl) * 24 + m];
    }
}

// fc2 column permutation: chunk c, band wn (0..3), tile t (0..3), slot s (0..7)
// -> original k in [0,1664)
__host__ __device__ __forceinline__ int perm_k(int c, int wn, int t, int s) {
    if (c < 8)  return (c * 4 + t) * 32 + wn * 8 + s;                    // W1
    if (c < 10) return 1024 + ((c - 8) * 16 + t * 4 + (s >> 1)) * 8      // W2
                       + wn * 2 + (s & 1);
    if (c < 12) return 1344 + ((c - 10) * 4 + t) * 32 + wn * 8 + s;      // W4
    if (t < 2)  return 1280 + (t * 4 + (s >> 1)) * 8 + wn * 2 + (s & 1); // W3
    return 1600 + ((t - 2) * 4 + (s >> 1)) * 8 + wn * 2 + (s & 1);       // W5
}

// split fc1_w (plain) and fc2_w (permuted) into fp16 padded layouts
__global__ void prep_wsplit_kernel(const float* __restrict__ f1w,
                                   const float* __restrict__ f2w) {
    int i = blockIdx.x * 256 + threadIdx.x;
    if (i < 128 * 136) {
        int k = i / 136, n = i - k * 136;
        float v = (n < 128) ? f1w[k * 128 + n] : 0.f;
        ((__half*)g_w1)[i] = __float2half_rn(v);
    } else {
        int j = i - 128 * 136;
        if (j < 13 * 128 * 136) {
            int c = j / (128 * 136), r = j - c * (128 * 136);
            int krow = r / 136, col = r - krow * 136;
            float v = 0.f;
            if (col < 128) {
                int wn = col >> 5, t = (col >> 3) & 3, s = col & 7;
                v = f2w[(size_t)krow * WNUM_ + perm_k(c, wn, t, s)];
            }
            ((__half*)g_w2)[(size_t)c * 17408 + krow * 136 + col] =
                __float2half_rn(v);
        }
    }
}

// ---------------------------------------------------------------------------
__launch_bounds__(THREADS, 1) __global__
void e3_main_kernel(const float* __restrict__ pair,
                    const int*   __restrict__ pidx,
                    const float* __restrict__ esh,
                    const int*   __restrict__ esrc,
                    const int*   __restrict__ edst,
                    const float* __restrict__ lng,
                    const float* __restrict__ lnb,
                    const float* __restrict__ f1b,
                    const float* __restrict__ f2b) {
    extern __shared__ char smem[];
    float* sA     = (float*)(smem + SM_A);
    float* f2b_s  = (float*)(smem + SM_F2B);
    float* f1b_s  = (float*)(smem + SM_F1B);
    const uint32_t smW   = smem_u32(smem + SM_W);
    const uint32_t smHHI = smem_u32(smem + SM_HHI);
    const uint32_t smHLO = smem_u32(smem + SM_HLO);

    const int tid = threadIdx.x, warp = tid >> 5, lane = tid & 31;
    const int eb0 = blockIdx.x * 64;
    const int warp_m = warp & 3, wn = warp >> 2;       // 4m x 4n
    const int gr = lane >> 2, tig = lane & 3;
    const int e0l = warp_m * 16 + gr, e1l = e0l + 8;

    // ---- issue cp.async for fc1 weights into slot 0 -------------------------
#pragma unroll
    for (int u = 0; u < 5; ++u) {
        int idx = tid + u * THREADS;
        if (idx < 2176) cpasync16(smW + idx * 16, (const char*)g_w1 + idx * 16);
    }
    CP_COMMIT();

    // ---- gather x into sA [64][128] f32; copy biases -----------------------
    for (int idx4 = tid; idx4 < 64 * 32; idx4 += THREADS) {
        int el = idx4 >> 5, c4 = idx4 & 31;
        int e = eb0 + el;
        int b = pidx[e], i = pidx[NE + e], j = pidx[2 * NE + e];
        ((float4*)sA)[el * 32 + c4] =
            ((const float4*)(pair + (size_t)(((b * L_) + i) * L_ + j) * DPAIR))[c4];
    }
    for (int i = tid; i < WNUM_; i += THREADS) f2b_s[i] = f2b[i];
    if (tid < 128) f1b_s[tid] = f1b[tid];
    __syncthreads();

    // ---- LayerNorm; write split x directly to hHi/hLo (warp: 4 edges) ------
    {
        float g0 = lng[lane], g1 = lng[lane + 32], g2 = lng[lane + 64], g3 = lng[lane + 96];
        float b0 = lnb[lane], b1 = lnb[lane + 32], b2 = lnb[lane + 64], b3 = lnb[lane + 96];
        for (int ee = 0; ee < 4; ++ee) {
            int el = warp * 4 + ee;
            const float* xr = sA + el * 128;
            float x0 = xr[lane], x1 = xr[lane + 32], x2 = xr[lane + 64], x3 = xr[lane + 96];
            float s = x0 + x1 + x2 + x3;
#pragma unroll
            for (int o = 16; o > 0; o >>= 1) s += __shfl_xor_sync(0xffffffffu, s, o);
            float mu = s * (1.f / 128.f);
            float d0 = x0 - mu, d1 = x1 - mu, d2 = x2 - mu, d3 = x3 - mu;
            float q = d0 * d0 + d1 * d1 + d2 * d2 + d3 * d3;
#pragma unroll
            for (int o = 16; o > 0; o >>= 1) q += __shfl_xor_sync(0xffffffffu, q, o);
            float rstd = rsqrtf(q * (1.f / 128.f) + 1e-5f);
            float v[4] = {d0 * rstd * g0 + b0, d1 * rstd * g1 + b1,
                          d2 * rstd * g2 + b2, d3 * rstd * g3 + b3};
#pragma unroll
            for (int p = 0; p < 4; ++p) {
                int col = lane + p * 32;
                __half h = __float2half_rn(v[p]);
                __half l = __float2half_rn(v[p] - __half2float(h));
                *(__half*)(smem + SM_HHI + el * 272 + col * 2) = h;
                *(__half*)(smem + SM_HLO + el * 272 + col * 2) = l;
            }
        }
    }
    __syncthreads();

    // ---- A-operand fragment preload (x hi/lo) -------------------------------
    uint32_t xh[8][4], xl[8][4];
    {
        int rowsel = warp_m * 16 + (lane & 15);
        uint32_t cextra = (lane & 16) ? 16 : 0;
#pragma unroll
        for (int ks = 0; ks < 8; ++ks) {
            uint32_t off = rowsel * 272 + ks * 32 + cextra;
            ldsm_x4(xh[ks], smHHI + off);
            ldsm_x4(xl[ks], smHLO + off);
        }
    }
    CP_WAIT(0);
    __syncthreads();

    // ---- fc1 MMA: h = relu(x @ fc1_w + b), 2-term fp16, fused epilogue -----
#pragma unroll
    for (int t = 0; t < 4; ++t) {
        float acc[4] = {0.f, 0.f, 0.f, 0.f};
        uint32_t col2 = (wn * 32 + t * 8) * 2;
#pragma unroll
        for (int kp = 0; kp < 4; ++kp) {
            uint32_t b4[4];
            ldsm_x4t(b4, smW + (kp * 32 + lane) * 272 + col2);
            mma_f16(acc, xh[2 * kp],     b4[0], b4[1]);
            mma_f16(acc, xh[2 * kp + 1], b4[2], b4[3]);
            mma_f16(acc, xl[2 * kp],     b4[0], b4[1]);
            mma_f16(acc, xl[2 * kp + 1], b4[2], b4[3]);
        }
#pragma unroll
        for (int e = 0; e < 2; ++e) {
            int row = warp_m * 16 + gr + e * 8;
            int col = wn * 32 + t * 8 + 2 * tig;
            float v0 = fmaxf(acc[2 * e]     + f1b_s[col],     0.f);
            float v1 = fmaxf(acc[2 * e + 1] + f1b_s[col + 1], 0.f);
            __half h0 = __float2half_rn(v0), h1 = __float2half_rn(v1);
            __half l0 = __float2half_rn(v0 - __half2float(h0));
            __half l1 = __float2half_rn(v1 - __half2float(h1));
            uint32_t off = row * 272 + col * 2;
            *(__half2*)(smem + SM_HHI + off) = __halves2half2(h0, h1);
            *(__half2*)(smem + SM_HLO + off) = __halves2half2(l0, l1);
        }
    }
    __syncthreads();   // all warps done reading fc1 w (slot0) + writing h

    // ---- prefetch fc2 chunks 0 and 1 ---------------------------------------
#pragma unroll
    for (int u = 0; u < 5; ++u) {
        int idx = tid + u * THREADS;
        if (idx < 2176) cpasync16(smW + idx * 16, (const char*)g_w2 + idx * 16);
    }
    CP_COMMIT();
#pragma unroll
    for (int u = 0; u < 5; ++u) {
        int idx = tid + u * THREADS;
        if (idx < 2176)
            cpasync16(smW + CHUNK_B + idx * 16,
                      (const char*)g_w2 + CHUNK_B + idx * 16);
    }
    CP_COMMIT();

    // ---- A coefficients (x in sA dead; pitch 184) ---------------------------
    for (int idx = tid; idx < 64 * 184; idx += THREADS) {
        int el = idx / 184, a = idx - el * 184;
        int e = eb0 + el;
        const float* F  = g_feats + edst[e] * DIRR;
        const float* SH = esh + e * 9;
        float val;
        if (a < 32) {
            val = PW0 * F[a] * SH[0];
        } else if (a < 40) {
            int u = a - 32;
            val = (PW0 * S3C) * (F[32 + u * 3] * SH[1] + F[33 + u * 3] * SH[2]
                                 + F[34 + u * 3] * SH[3]);
        } else if (a < 136) {
            int t = a - 40; int u = t / 3, m = t - u * 3;
            val = (PW1 * S3C) * F[u] * SH[1 + m];
        } else if (a < 160) {
            int t = a - 136; int u = t / 3, m = t - u * 3;
            val = (PW1 * S3C) * F[32 + u * 3 + m] * SH[0];
        } else {
            int t = a - 160; int u = t / 3, m = t - u * 3;
            float xx = F[32 + u * 3], xy = F[33 + u * 3], xz = F[34 + u * 3];
            float s0 = SH[4], s1 = SH[5], s2 = SH[6], s3v = SH[7], s4 = SH[8];
            float t5;
            if (m == 0)      t5 = (xz * s0 + xy * s1 - xx * s4) * S3C - xx * s2 * (1.f / 3.f);
            else if (m == 1) t5 = (xx * s1 + xz * s3v) * S3C + xy * s2 * (2.f / 3.f);
            else             t5 = (xx * s0 + xy * s3v + xz * s4) * S3C - xz * s2 * (1.f / 3.f);
            val = (PW1 * F121) * t5;
        }
        sA[el * 184 + a] = val;
    }
    __syncthreads();   // h + A complete

    // ---- reload A-operand fragments (now h hi/lo) ----------------------------
    {
        int rowsel = warp_m * 16 + (lane & 15);
        uint32_t cextra = (lane & 16) ? 16 : 0;
#pragma unroll
        for (int ks = 0; ks < 8; ++ks) {
            uint32_t off = rowsel * 272 + ks * 32 + cextra;
            ldsm_x4(xh[ks], smHHI + off);
            ldsm_x4(xl[ks], smHLO + off);
        }
    }

    // ---- fc2 chunk loop (13 chunks of 128 permuted cols) --------------------
    float conv0[4]  = {0.f, 0.f, 0.f, 0.f};      // [e*2 + j], out0 col 8*wn+2tig+j
    float conv1[12];                              // [e*6 + j*3 + m]
#pragma unroll
    for (int o = 0; o < 12; ++o) conv1[o] = 0.f;
    const float* Arow0 = sA + e0l * 184;
    const float* Arow1 = sA + e1l * 184;

    for (int c = 0; c < 13; ++c) {
        if (c < 12) { CP_WAIT(1); } else { CP_WAIT(0); }
        __syncthreads();

        // prefetch chunk c+2 into slot (c+2)%3 (its last reader synced above)
        if (c + 2 < 13) {
            const char* gsrc = (const char*)g_w2 + (size_t)(c + 2) * CHUNK_B;
            uint32_t sdst = smW + (uint32_t)(((c + 2) % 3) * CHUNK_B);
#pragma unroll
            for (int u = 0; u < 5; ++u) {
                int idx = tid + u * THREADS;
                if (idx < 2176) cpasync16(sdst + idx * 16, gsrc + idx * 16);
            }
            CP_COMMIT();
        }

        const uint32_t buf = smW + (uint32_t)((c % 3) * CHUNK_B);
#pragma unroll
        for (int t = 0; t < 4; ++t) {
            float acc[4] = {0.f, 0.f, 0.f, 0.f};
            uint32_t col2 = (wn * 32 + t * 8) * 2;
#pragma unroll
            for (int kp = 0; kp < 4; ++kp) {
                uint32_t b4[4];
                ldsm_x4t(b4, buf + (kp * 32 + lane) * 272 + col2);
                mma_f16(acc, xh[2 * kp],     b4[0], b4[1]);
                mma_f16(acc, xh[2 * kp + 1], b4[2], b4[3]);
                mma_f16(acc, xl[2 * kp],     b4[0], b4[1]);
                mma_f16(acc, xl[2 * kp + 1], b4[2], b4[3]);
            }
            // decode permuted region and contract
            if (c < 8 || (c >= 10 && c < 12)) {            // W1 / W4 -> conv0
                int u    = (c < 8) ? (c * 4 + t) : (32 + (c - 10) * 4 + t);
                int kb   = (c < 8) ? ((c * 4 + t) * 32 + wn * 8)
                                   : (1344 + ((c - 10) * 4 + t) * 32 + wn * 8);
                float b0v = f2b_s[kb + 2 * tig], b1v = f2b_s[kb + 2 * tig + 1];
                float a0 = Arow0[u], a1 = Arow1[u];
                conv0[0] += a0 * (acc[0] + b0v);
                conv0[1] += a0 * (acc[1] + b1v);
                conv0[2] += a1 * (acc[2] + b0v);
                conv0[3] += a1 * (acc[3] + b1v);
            } else {                                       // W2 / W3 / W5 -> conv1
                int base, u0, kb;
                if (c < 10) {          // W2
                    u0 = (c - 8) * 16 + t * 4 + tig; base = 40;
                    kb = 1024 + u0 * 8 + wn * 2;
                } else if (t < 2) {    // W3 (c == 12, tiles 0-1)
                    u0 = t * 4 + tig;  base = 136;
                    kb = 1280 + u0 * 8 + wn * 2;
                } else {               // W5 (c == 12, tiles 2-3)
                    u0 = (t - 2) * 4 + tig; base = 160;
                    kb = 1600 + u0 * 8 + wn * 2;
                }
                float b0v = f2b_s[kb], b1v = f2b_s[kb + 1];
                float p00 = acc[0] + b0v, p01 = acc[1] + b1v;
                float p10 = acc[2] + b0v, p11 = acc[3] + b1v;
                const float* A0 = Arow0 + base + u0 * 3;
                const float* A1 = Arow1 + base + u0 * 3;
#pragma unroll
                for (int m = 0; m < 3; ++m) {
                    conv1[m]     += A0[m] * p00;
                    conv1[3 + m] += A0[m] * p01;
                    conv1[6 + m] += A1[m] * p10;
                    conv1[9 + m] += A1[m] * p11;
                }
            }
        }
    }

    // ---- conv1: reduce across tig (lanes xor 1,2), then scatter -------------
#pragma unroll
    for (int o = 0; o < 12; ++o) {
        conv1[o] += __shfl_xor_sync(0xffffffffu, conv1[o], 1);
        conv1[o] += __shfl_xor_sync(0xffffffffu, conv1[o], 2);
    }

    {
        int s0 = esrc[eb0 + e0l] * DIRR;
        int s1 = esrc[eb0 + e1l] * DIRR;
#pragma unroll
        for (int j = 0; j < 2; ++j) {
            int v = wn * 8 + 2 * tig + j;
            atomicAdd(&g_sums[s0 + v], conv0[j]);
            atomicAdd(&g_sums[s1 + v], conv0[2 + j]);
        }
        if (tig == 0) {
#pragma unroll
            for (int j = 0; j < 2; ++j)
#pragma unroll
                for (int m = 0; m < 3; ++m) {
                    int o = 32 + (wn * 2 + j) * 3 + m;
                    atomicAdd(&g_sums[s0 + o], conv1[j * 3 + m]);
                    atomicAdd(&g_sums[s1 + o], conv1[6 + j * 3 + m]);
                }
        }
    }
    if (tid < 64) atomicAdd(&g_cnt[esrc[eb0 + tid]], 1.f);
}

// ---------------------------------------------------------------------------
__global__ void finalize_kernel(const float* __restrict__ node,
                                const float* __restrict__ l1,
                                const float* __restrict__ pnw,
                                const float* __restrict__ pnb,
                                float* __restrict__ out) {
    int n = blockIdx.x;
    __shared__ float o0[32];
    float inv = 1.f / fmaxf(g_cnt[n], 1.f);
    if (threadIdx.x < 32) o0[threadIdx.x] = g_sums[n * DIRR + threadIdx.x] * inv;
    __syncthreads();
    int d = threadIdx.x;
    float acc = pnb[d];
#pragma unroll
    for (int u = 0; u < 32; ++u) acc += o0[u] * pnw[u * DNODE + d];
    out[n * DNODE + d] = acc + node[n * DNODE + d];
    if (d < 24)
        out[NNODE * DNODE + n * 24 + d] = g_sums[n * DIRR + 32 + d] * inv + l1[n * 24 + d];
}

// ---------------------------------------------------------------------------
extern "C" void kernel_launch(void* const* d_in, const int* in_sizes, int n_in,
                              void* d_out, int out_size) {
    const float* node = (const float*)d_in[0];
    const float* pair = (const float*)d_in[1];
    const float* l1   = (const float*)d_in[2];
    const float* esh  = (const float*)d_in[3];
    const float* pl0w = (const float*)d_in[4];
    const float* pl0b = (const float*)d_in[5];
    const float* pnw  = (const float*)d_in[6];
    const float* pnb  = (const float*)d_in[7];
    const float* lng  = (const float*)d_in[8];
    const float* lnb  = (const float*)d_in[9];
    const float* f1w  = (const float*)d_in[10];
    const float* f1b  = (const float*)d_in[11];
    const float* f2w  = (const float*)d_in[12];
    const float* f2b  = (const float*)d_in[13];
    const int*   pidx = (const int*)d_in[14];
    const int*   esrc = (const int*)d_in[15];
    const int*   edst = (const int*)d_in[16];
    float* out = (float*)d_out;

    cudaFuncSetAttribute(e3_main_kernel,
                         cudaFuncAttributeMaxDynamicSharedMemorySize, SM_TOTAL);

    prep_zero_kernel<<<57, 1024>>>();
    prep_proj_kernel<<<64, 256>>>(node, pl0w, pl0b, l1);
    prep_wsplit_kernel<<<952, 256>>>(f1w, f2w);
    e3_main_kernel<<<NE / 64, THREADS, SM_TOTAL>>>(pair, pidx, esh, esrc, edst,
                                                   lng, lnb, f1b, f2b);
    finalize_kernel<<<NNODE, 256>>>(node, l1, pnw, pnb, out);
}

// round 9
// speedup vs baseline: 5.6936x; 1.3127x over previous
#include <cuda_runtime.h>
#include <cuda_fp16.h>
#include <cstdint>

#define B_     4
#define L_     256
#define NNODE  1024
#define DNODE  256
#define DPAIR  128
#define NE     65536
#define M0_    32
#define DIRR   56
#define WNUM_  1664

#define PW0   0.15811388300841897f
#define PW1   0.25f
#define S3C   0.5773502691896258f
#define F121  0.5477225575051661f

// device scratch (no allocations allowed)
__device__ float g_feats[NNODE * DIRR];
__device__ float g_sums [NNODE * DIRR];
__device__ float g_cnt  [NNODE];
// pre-split weights (fp16), padded + column-permuted layouts
__device__ uint4 g_w1[2176];     // fc1: 128 x 136 fp16 = 34,816 B
__device__ uint4 g_w2[28288];    // fc2: 13 chunks x 128 x 136 fp16 = 452,608 B

// ---------------- plain-PTX helpers (sm_80-level, safe on sm_103) ----------
__device__ __forceinline__ uint32_t smem_u32(const void* p) {
    uint32_t a;
    asm("{ .reg .u64 t; cvta.to.shared.u64 t, %1; cvt.u32.u64 %0, t; }"
        : "=r"(a) : "l"(p));
    return a;
}
__device__ __forceinline__ void ldsm_x4(uint32_t* r, uint32_t addr) {
    asm volatile("ldmatrix.sync.aligned.m8n8.x4.shared.b16 {%0,%1,%2,%3}, [%4];"
        : "=r"(r[0]), "=r"(r[1]), "=r"(r[2]), "=r"(r[3]) : "r"(addr));
}
__device__ __forceinline__ void ldsm_x4t(uint32_t* r, uint32_t addr) {
    asm volatile("ldmatrix.sync.aligned.m8n8.x4.trans.shared.b16 {%0,%1,%2,%3}, [%4];"
        : "=r"(r[0]), "=r"(r[1]), "=r"(r[2]), "=r"(r[3]) : "r"(addr));
}
__device__ __forceinline__ void mma_f16(float* d, const uint32_t* a,
                                        uint32_t b0, uint32_t b1) {
    asm volatile("mma.sync.aligned.m16n8k16.row.col.f32.f16.f16.f32 "
        "{%0,%1,%2,%3}, {%4,%5,%6,%7}, {%8,%9}, {%0,%1,%2,%3};"
        : "+f"(d[0]), "+f"(d[1]), "+f"(d[2]), "+f"(d[3])
        : "r"(a[0]), "r"(a[1]), "r"(a[2]), "r"(a[3]), "r"(b0), "r"(b1));
}
__device__ __forceinline__ void cpasync16(uint32_t s, const void* g) {
    asm volatile("cp.async.cg.shared.global [%0], [%1], 16;" :: "r"(s), "l"(g));
}
#define CP_COMMIT() asm volatile("cp.async.commit_group;" ::: "memory")
#define CP_WAIT(N)  asm volatile("cp.async.wait_group %0;" :: "n"(N) : "memory")

// smem layout (bytes) -- 64 edges per CTA
#define SM_A     0        // 64x184 f32 A-coeffs (x staging 64x128 f32 first) = 47104
#define SM_HHI   47104    // 64x136 fp16 = 17408 (pitch 272 B)
#define SM_HLO   64512    // x lo (fc1 only) = 17408
#define SM_W     81920    // 3 x 34816 = 104448 (slot0 doubles as fc1 buffer)
#define SM_F2B   186368   // 1664 f32 = 6656
#define SM_F1B   193024   // 128 f32 = 512
#define SM_TOTAL 193536

#define THREADS  512
#define CHUNK_B  34816    // one fc2 chunk: 128 rows x 136 fp16 cols

// ---------------------------------------------------------------------------
__global__ void prep_zero_kernel() {
    int i = blockIdx.x * 1024 + threadIdx.x;
    if (i < NNODE * DIRR) g_sums[i] = 0.f;
    else if (i < NNODE * DIRR + NNODE) g_cnt[i - NNODE * DIRR] = 0.f;
}

__global__ __launch_bounds__(256) void prep_proj_kernel(
        const float* __restrict__ node, const float* __restrict__ w,
        const float* __restrict__ b,    const float* __restrict__ l1) {
    __shared__ float sw[DNODE * M0_];
    __shared__ float sx[16 * DNODE];
    int tid = threadIdx.x, n0 = blockIdx.x * 16;
    for (int i = tid; i < DNODE * M0_; i += 256) sw[i] = w[i];
    for (int i = tid; i < 16 * DNODE; i += 256) sx[i] = node[n0 * DNODE + i];
    __syncthreads();
    int warp = tid >> 5, lane = tid & 31;
    for (int r = 0; r < 2; ++r) {
        int nl = warp * 2 + r;
        float acc = b[lane];
        const float* x = sx + nl * DNODE;
#pragma unroll 8
        for (int k = 0; k < DNODE; ++k) acc += x[k] * sw[k * M0_ + lane];
        g_feats[(n0 + nl) * DIRR + lane] = acc;
    }
    for (int i = tid; i < 16 * 24; i += 256) {
        int nl = i / 24, m = i - nl * 24;
        g_feats[(n0 + nl) * DIRR + M0_ + m] = l1[(n0 + nl) * 24 + m];
    }
}

// fc2 column permutation: chunk c, band wn (0..3), tile t (0..3), slot s (0..7)
// -> original k in [0,1664)
__host__ __device__ __forceinline__ int perm_k(int c, int wn, int t, int s) {
    if (c < 8)  return (c * 4 + t) * 32 + wn * 8 + s;                    // W1
    if (c < 10) return 1024 + ((c - 8) * 16 + t * 4 + (s >> 1)) * 8      // W2
                       + wn * 2 + (s & 1);
    if (c < 12) return 1344 + ((c - 10) * 4 + t) * 32 + wn * 8 + s;      // W4
    if (t < 2)  return 1280 + (t * 4 + (s >> 1)) * 8 + wn * 2 + (s & 1); // W3
    return 1600 + ((t - 2) * 4 + (s >> 1)) * 8 + wn * 2 + (s & 1);       // W5
}

// split fc1_w (plain) and fc2_w (permuted) into fp16 padded layouts
__global__ void prep_wsplit_kernel(const float* __restrict__ f1w,
                                   const float* __restrict__ f2w) {
    int i = blockIdx.x * 256 + threadIdx.x;
    if (i < 128 * 136) {
        int k = i / 136, n = i - k * 136;
        float v = (n < 128) ? f1w[k * 128 + n] : 0.f;
        ((__half*)g_w1)[i] = __float2half_rn(v);
    } else {
        int j = i - 128 * 136;
        if (j < 13 * 128 * 136) {
            int c = j / (128 * 136), r = j - c * (128 * 136);
            int krow = r / 136, col = r - krow * 136;
            float v = 0.f;
            if (col < 128) {
                int wn = col >> 5, t = (col >> 3) & 3, s = col & 7;
                v = f2w[(size_t)krow * WNUM_ + perm_k(c, wn, t, s)];
            }
            ((__half*)g_w2)[(size_t)c * 17408 + krow * 136 + col] =
                __float2half_rn(v);
        }
    }
}

// ---------------------------------------------------------------------------
__launch_bounds__(THREADS, 1) __global__
void e3_main_kernel(const float* __restrict__ pair,
                    const int*   __restrict__ pidx,
                    const float* __restrict__ esh,
                    const int*   __restrict__ esrc,
                    const int*   __restrict__ edst,
                    const float* __restrict__ lng,
                    const float* __restrict__ lnb,
                    const float* __restrict__ f1b,
                    const float* __restrict__ f2b) {
    extern __shared__ char smem[];
    float* sA     = (float*)(smem + SM_A);
    float* f2b_s  = (float*)(smem + SM_F2B);
    float* f1b_s  = (float*)(smem + SM_F1B);
    const uint32_t smW   = smem_u32(smem + SM_W);
    const uint32_t smHHI = smem_u32(smem + SM_HHI);
    const uint32_t smHLO = smem_u32(smem + SM_HLO);

    const int tid = threadIdx.x, warp = tid >> 5, lane = tid & 31;
    const int eb0 = blockIdx.x * 64;
    const int warp_m = warp & 3, wn = warp >> 2;       // 4m x 4n
    const int gr = lane >> 2, tig = lane & 3;
    const int e0l = warp_m * 16 + gr, e1l = e0l + 8;

    // ---- issue cp.async for fc1 weights into slot 0 -------------------------
#pragma unroll
    for (int u = 0; u < 5; ++u) {
        int idx = tid + u * THREADS;
        if (idx < 2176) cpasync16(smW + idx * 16, (const char*)g_w1 + idx * 16);
    }
    CP_COMMIT();

    // ---- gather x into sA [64][128] f32; copy biases -----------------------
    for (int idx4 = tid; idx4 < 64 * 32; idx4 += THREADS) {
        int el = idx4 >> 5, c4 = idx4 & 31;
        int e = eb0 + el;
        int b = pidx[e], i = pidx[NE + e], j = pidx[2 * NE + e];
        ((float4*)sA)[el * 32 + c4] =
            ((const float4*)(pair + (size_t)(((b * L_) + i) * L_ + j) * DPAIR))[c4];
    }
    for (int i = tid; i < WNUM_; i += THREADS) f2b_s[i] = f2b[i];
    if (tid < 128) f1b_s[tid] = f1b[tid];
    __syncthreads();

    // ---- LayerNorm; write split x to hHi/hLo (warp: 4 edges) ---------------
    {
        float g0 = lng[lane], g1 = lng[lane + 32], g2 = lng[lane + 64], g3 = lng[lane + 96];
        float b0 = lnb[lane], b1 = lnb[lane + 32], b2 = lnb[lane + 64], b3 = lnb[lane + 96];
        for (int ee = 0; ee < 4; ++ee) {
            int el = warp * 4 + ee;
            const float* xr = sA + el * 128;
            float x0 = xr[lane], x1 = xr[lane + 32], x2 = xr[lane + 64], x3 = xr[lane + 96];
            float s = x0 + x1 + x2 + x3;
#pragma unroll
            for (int o = 16; o > 0; o >>= 1) s += __shfl_xor_sync(0xffffffffu, s, o);
            float mu = s * (1.f / 128.f);
            float d0 = x0 - mu, d1 = x1 - mu, d2 = x2 - mu, d3 = x3 - mu;
            float q = d0 * d0 + d1 * d1 + d2 * d2 + d3 * d3;
#pragma unroll
            for (int o = 16; o > 0; o >>= 1) q += __shfl_xor_sync(0xffffffffu, q, o);
            float rstd = rsqrtf(q * (1.f / 128.f) + 1e-5f);
            float v[4] = {d0 * rstd * g0 + b0, d1 * rstd * g1 + b1,
                          d2 * rstd * g2 + b2, d3 * rstd * g3 + b3};
#pragma unroll
            for (int p = 0; p < 4; ++p) {
                int col = lane + p * 32;
                __half h = __float2half_rn(v[p]);
                __half l = __float2half_rn(v[p] - __half2float(h));
                *(__half*)(smem + SM_HHI + el * 272 + col * 2) = h;
                *(__half*)(smem + SM_HLO + el * 272 + col * 2) = l;
            }
        }
    }
    __syncthreads();

    // ---- A-operand fragment preload (x hi/lo) -------------------------------
    uint32_t xh[8][4], xl[8][4];
    {
        int rowsel = warp_m * 16 + (lane & 15);
        uint32_t cextra = (lane & 16) ? 16 : 0;
#pragma unroll
        for (int ks = 0; ks < 8; ++ks) {
            uint32_t off = rowsel * 272 + ks * 32 + cextra;
            ldsm_x4(xh[ks], smHHI + off);
            ldsm_x4(xl[ks], smHLO + off);
        }
    }
    CP_WAIT(0);
    __syncthreads();

    // ---- fc1 MMA: h = relu(x @ fc1_w + b), 2-term fp16, fused epilogue -----
#pragma unroll
    for (int t = 0; t < 4; ++t) {
        float accE[4] = {0.f, 0.f, 0.f, 0.f};
        float accO[4] = {0.f, 0.f, 0.f, 0.f};
        uint32_t col2 = (wn * 32 + t * 8) * 2;
#pragma unroll
        for (int kp = 0; kp < 4; ++kp) {
            float* acc = (kp & 1) ? accO : accE;
            uint32_t b4[4];
            ldsm_x4t(b4, smW + (kp * 32 + lane) * 272 + col2);
            mma_f16(acc, xh[2 * kp],     b4[0], b4[1]);
            mma_f16(acc, xh[2 * kp + 1], b4[2], b4[3]);
            mma_f16(acc, xl[2 * kp],     b4[0], b4[1]);
            mma_f16(acc, xl[2 * kp + 1], b4[2], b4[3]);
        }
#pragma unroll
        for (int e = 0; e < 2; ++e) {
            int row = warp_m * 16 + gr + e * 8;
            int col = wn * 32 + t * 8 + 2 * tig;
            float v0 = fmaxf(accE[2 * e]     + accO[2 * e]     + f1b_s[col],     0.f);
            float v1 = fmaxf(accE[2 * e + 1] + accO[2 * e + 1] + f1b_s[col + 1], 0.f);
            __half h0 = __float2half_rn(v0), h1 = __float2half_rn(v1);
            uint32_t off = row * 272 + col * 2;
            *(__half2*)(smem + SM_HHI + off) = __halves2half2(h0, h1);
        }
    }
    __syncthreads();   // all warps done reading fc1 w (slot0) + writing h

    // ---- prefetch fc2 chunks 0 and 1 ---------------------------------------
#pragma unroll
    for (int u = 0; u < 5; ++u) {
        int idx = tid + u * THREADS;
        if (idx < 2176) cpasync16(smW + idx * 16, (const char*)g_w2 + idx * 16);
    }
    CP_COMMIT();
#pragma unroll
    for (int u = 0; u < 5; ++u) {
        int idx = tid + u * THREADS;
        if (idx < 2176)
            cpasync16(smW + CHUNK_B + idx * 16,
                      (const char*)g_w2 + CHUNK_B + idx * 16);
    }
    CP_COMMIT();

    // ---- A coefficients: warp handles 4 edges, lane-strided (no int div) ----
#pragma unroll 1
    for (int ee = 0; ee < 4; ++ee) {
        int el = warp * 4 + ee;
        int e  = eb0 + el;
        const float* F  = g_feats + edst[e] * DIRR;
        const float* SH = esh + e * 9;
        float* Adst = sA + el * 184;
        for (int a = lane; a < 184; a += 32) {
            float val;
            if (a < 32) {
                val = PW0 * F[a] * SH[0];
            } else if (a < 40) {
                int u = a - 32;
                val = (PW0 * S3C) * (F[32 + u * 3] * SH[1] + F[33 + u * 3] * SH[2]
                                     + F[34 + u * 3] * SH[3]);
            } else if (a < 136) {
                int t = a - 40; int u = t / 3, m = t - u * 3;
                val = (PW1 * S3C) * F[u] * SH[1 + m];
            } else if (a < 160) {
                int t = a - 136; int u = t / 3, m = t - u * 3;
                val = (PW1 * S3C) * F[32 + u * 3 + m] * SH[0];
            } else {
                int t = a - 160; int u = t / 3, m = t - u * 3;
                float xx = F[32 + u * 3], xy = F[33 + u * 3], xz = F[34 + u * 3];
                float s0 = SH[4], s1 = SH[5], s2 = SH[6], s3v = SH[7], s4 = SH[8];
                float t5;
                if (m == 0)      t5 = (xz * s0 + xy * s1 - xx * s4) * S3C - xx * s2 * (1.f / 3.f);
                else if (m == 1) t5 = (xx * s1 + xz * s3v) * S3C + xy * s2 * (2.f / 3.f);
                else             t5 = (xx * s0 + xy * s3v + xz * s4) * S3C - xz * s2 * (1.f / 3.f);
                val = (PW1 * F121) * t5;
            }
            Adst[a] = val;
        }
    }
    __syncthreads();   // h + A complete

    // ---- reload A-operand fragments (h hi only) ------------------------------
    {
        int rowsel = warp_m * 16 + (lane & 15);
        uint32_t cextra = (lane & 16) ? 16 : 0;
#pragma unroll
        for (int ks = 0; ks < 8; ++ks)
            ldsm_x4(xh[ks], smHHI + rowsel * 272 + ks * 32 + cextra);
    }

    // ---- fc2 chunk loop (13 chunks, single-term fp16) ------------------------
    float conv0[4]  = {0.f, 0.f, 0.f, 0.f};      // [e*2 + j], out0 col 8*wn+2tig+j
    float conv1[12];                              // [e*6 + j*3 + m]
#pragma unroll
    for (int o = 0; o < 12; ++o) conv1[o] = 0.f;
    const float* Arow0 = sA + e0l * 184;
    const float* Arow1 = sA + e1l * 184;

    for (int c = 0; c < 13; ++c) {
        if (c < 12) { CP_WAIT(1); } else { CP_WAIT(0); }
        __syncthreads();

        // prefetch chunk c+2 into slot (c+2)%3 (its last reader synced above)
        if (c + 2 < 13) {
            const char* gsrc = (const char*)g_w2 + (size_t)(c + 2) * CHUNK_B;
            uint32_t sdst = smW + (uint32_t)(((c + 2) % 3) * CHUNK_B);
#pragma unroll
            for (int u = 0; u < 5; ++u) {
                int idx = tid + u * THREADS;
                if (idx < 2176) cpasync16(sdst + idx * 16, gsrc + idx * 16);
            }
            CP_COMMIT();
        }

        const uint32_t buf = smW + (uint32_t)((c % 3) * CHUNK_B);
#pragma unroll
        for (int t = 0; t < 4; ++t) {
            float accE[4] = {0.f, 0.f, 0.f, 0.f};
            float accO[4] = {0.f, 0.f, 0.f, 0.f};
            uint32_t col2 = (wn * 32 + t * 8) * 2;
            uint32_t b0[4], b1[4], b2[4], b3[4];
            ldsm_x4t(b0, buf + (0 * 32 + lane) * 272 + col2);
            ldsm_x4t(b1, buf + (1 * 32 + lane) * 272 + col2);
            ldsm_x4t(b2, buf + (2 * 32 + lane) * 272 + col2);
            ldsm_x4t(b3, buf + (3 * 32 + lane) * 272 + col2);
            mma_f16(accE, xh[0], b0[0], b0[1]);
            mma_f16(accO, xh[1], b0[2], b0[3]);
            mma_f16(accE, xh[2], b1[0], b1[1]);
            mma_f16(accO, xh[3], b1[2], b1[3]);
            mma_f16(accE, xh[4], b2[0], b2[1]);
            mma_f16(accO, xh[5], b2[2], b2[3]);
            mma_f16(accE, xh[6], b3[0], b3[1]);
            mma_f16(accO, xh[7], b3[2], b3[3]);
            float acc[4];
#pragma unroll
            for (int q = 0; q < 4; ++q) acc[q] = accE[q] + accO[q];

            // decode permuted region and contract
            if (c < 8 || (c >= 10 && c < 12)) {            // W1 / W4 -> conv0
                int u    = (c < 8) ? (c * 4 + t) : (32 + (c - 10) * 4 + t);
                int kb   = (c < 8) ? ((c * 4 + t) * 32 + wn * 8)
                                   : (1344 + ((c - 10) * 4 + t) * 32 + wn * 8);
                float b0v = f2b_s[kb + 2 * tig], b1v = f2b_s[kb + 2 * tig + 1];
                float a0 = Arow0[u], a1 = Arow1[u];
                conv0[0] += a0 * (acc[0] + b0v);
                conv0[1] += a0 * (acc[1] + b1v);
                conv0[2] += a1 * (acc[2] + b0v);
                conv0[3] += a1 * (acc[3] + b1v);
            } else {                                       // W2 / W3 / W5 -> conv1
                int base, u0, kb;
                if (c < 10) {          // W2
                    u0 = (c - 8) * 16 + t * 4 + tig; base = 40;
                    kb = 1024 + u0 * 8 + wn * 2;
                } else if (t < 2) {    // W3 (c == 12, tiles 0-1)
                    u0 = t * 4 + tig;  base = 136;
                    kb = 1280 + u0 * 8 + wn * 2;
                } else {               // W5 (c == 12, tiles 2-3)
                    u0 = (t - 2) * 4 + tig; base = 160;
                    kb = 1600 + u0 * 8 + wn * 2;
                }
                float b0v = f2b_s[kb], b1v = f2b_s[kb + 1];
                float p00 = acc[0] + b0v, p01 = acc[1] + b1v;
                float p10 = acc[2] + b0v, p11 = acc[3] + b1v;
                const float* A0 = Arow0 + base + u0 * 3;
                const float* A1 = Arow1 + base + u0 * 3;
#pragma unroll
                for (int m = 0; m < 3; ++m) {
                    conv1[m]     += A0[m] * p00;
                    conv1[3 + m] += A0[m] * p01;
                    conv1[6 + m] += A1[m] * p10;
                    conv1[9 + m] += A1[m] * p11;
                }
            }
        }
    }

    // ---- conv1: reduce across tig (lanes xor 1,2), then scatter -------------
#pragma unroll
    for (int o = 0; o < 12; ++o) {
        conv1[o] += __shfl_xor_sync(0xffffffffu, conv1[o], 1);
        conv1[o] += __shfl_xor_sync(0xffffffffu, conv1[o], 2);
    }

    {
        int s0 = esrc[eb0 + e0l] * DIRR;
        int s1 = esrc[eb0 + e1l] * DIRR;
#pragma unroll
        for (int j = 0; j < 2; ++j) {
            int v = wn * 8 + 2 * tig + j;
            atomicAdd(&g_sums[s0 + v], conv0[j]);
            atomicAdd(&g_sums[s1 + v], conv0[2 + j]);
        }
        if (tig == 0) {
#pragma unroll
            for (int j = 0; j < 2; ++j)
#pragma unroll
                for (int m = 0; m < 3; ++m) {
                    int o = 32 + (wn * 2 + j) * 3 + m;
                    atomicAdd(&g_sums[s0 + o], conv1[j * 3 + m]);
                    atomicAdd(&g_sums[s1 + o], conv1[6 + j * 3 + m]);
                }
        }
    }
    if (tid < 64) atomicAdd(&g_cnt[esrc[eb0 + tid]], 1.f);
}

// ---------------------------------------------------------------------------
__global__ void finalize_kernel(const float* __restrict__ node,
                                const float* __restrict__ l1,
                                const float* __restrict__ pnw,
                                const float* __restrict__ pnb,
                                float* __restrict__ out) {
    int n = blockIdx.x;
    __shared__ float o0[32];
    float inv = 1.f / fmaxf(g_cnt[n], 1.f);
    if (threadIdx.x < 32) o0[threadIdx.x] = g_sums[n * DIRR + threadIdx.x] * inv;
    __syncthreads();
    int d = threadIdx.x;
    float acc = pnb[d];
#pragma unroll
    for (int u = 0; u < 32; ++u) acc += o0[u] * pnw[u * DNODE + d];
    out[n * DNODE + d] = acc + node[n * DNODE + d];
    if (d < 24)
        out[NNODE * DNODE + n * 24 + d] = g_sums[n * DIRR + 32 + d] * inv + l1[n * 24 + d];
}

// ---------------------------------------------------------------------------
extern "C" void kernel_launch(void* const* d_in, const int* in_sizes, int n_in,
                              void* d_out, int out_size) {
    const float* node = (const float*)d_in[0];
    const float* pair = (const float*)d_in[1];
    const float* l1   = (const float*)d_in[2];
    const float* esh  = (const float*)d_in[3];
    const float* pl0w = (const float*)d_in[4];
    const float* pl0b = (const float*)d_in[5];
    const float* pnw  = (const float*)d_in[6];
    const float* pnb  = (const float*)d_in[7];
    const float* lng  = (const float*)d_in[8];
    const float* lnb  = (const float*)d_in[9];
    const float* f1w  = (const float*)d_in[10];
    const float* f1b  = (const float*)d_in[11];
    const float* f2w  = (const float*)d_in[12];
    const float* f2b  = (const float*)d_in[13];
    const int*   pidx = (const int*)d_in[14];
    const int*   esrc = (const int*)d_in[15];
    const int*   edst = (const int*)d_in[16];
    float* out = (float*)d_out;

    cudaFuncSetAttribute(e3_main_kernel,
                         cudaFuncAttributeMaxDynamicSharedMemorySize, SM_TOTAL);

    prep_zero_kernel<<<57, 1024>>>();
    prep_proj_kernel<<<64, 256>>>(node, pl0w, pl0b, l1);
    prep_wsplit_kernel<<<952, 256>>>(f1w, f2w);
    e3_main_kernel<<<NE / 64, THREADS, SM_TOTAL>>>(pair, pidx, esh, esrc, edst,
                                                   lng, lnb, f1b, f2b);
    finalize_kernel<<<NNODE, 256>>>(node, l1, pnw, pnb, out);
}

// round 11
// speedup vs baseline: 6.0730x; 1.0666x over previous
#include <cuda_runtime.h>
#include <cuda_fp16.h>
#include <cstdint>

#define B_     4
#define L_     256
#define NNODE  1024
#define DNODE  256
#define DPAIR  128
#define NE     65536
#define M0_    32
#define DIRR   56
#define WNUM_  1664

#define PW0   0.15811388300841897f
#define PW1   0.25f
#define S3C   0.5773502691896258f
#define F121  0.5477225575051661f

// device scratch (no allocations allowed)
__device__ float g_feats[NNODE * DIRR];
__device__ float g_sums [NNODE * DIRR];
__device__ float g_cnt  [NNODE];
// pre-split weights (fp16), padded + column-permuted layouts
__device__ uint4 g_w1[2176];     // fc1: 128 x 136 fp16 = 34,816 B
__device__ uint4 g_w2[28288];    // fc2: 13 chunks x 128 x 136 fp16 = 452,608 B

// ---------------- plain-PTX helpers (sm_80-level, safe on sm_103) ----------
__device__ __forceinline__ uint32_t smem_u32(const void* p) {
    uint32_t a;
    asm("{ .reg .u64 t; cvta.to.shared.u64 t, %1; cvt.u32.u64 %0, t; }"
        : "=r"(a) : "l"(p));
    return a;
}
__device__ __forceinline__ void ldsm_x4(uint32_t* r, uint32_t addr) {
    asm volatile("ldmatrix.sync.aligned.m8n8.x4.shared.b16 {%0,%1,%2,%3}, [%4];"
        : "=r"(r[0]), "=r"(r[1]), "=r"(r[2]), "=r"(r[3]) : "r"(addr));
}
__device__ __forceinline__ void ldsm_x4t(uint32_t* r, uint32_t addr) {
    asm volatile("ldmatrix.sync.aligned.m8n8.x4.trans.shared.b16 {%0,%1,%2,%3}, [%4];"
        : "=r"(r[0]), "=r"(r[1]), "=r"(r[2]), "=r"(r[3]) : "r"(addr));
}
__device__ __forceinline__ void mma_f16(float* d, const uint32_t* a,
                                        uint32_t b0, uint32_t b1) {
    asm volatile("mma.sync.aligned.m16n8k16.row.col.f32.f16.f16.f32 "
        "{%0,%1,%2,%3}, {%4,%5,%6,%7}, {%8,%9}, {%0,%1,%2,%3};"
        : "+f"(d[0]), "+f"(d[1]), "+f"(d[2]), "+f"(d[3])
        : "r"(a[0]), "r"(a[1]), "r"(a[2]), "r"(a[3]), "r"(b0), "r"(b1));
}
__device__ __forceinline__ void cpasync16(uint32_t s, const void* g) {
    asm volatile("cp.async.cg.shared.global [%0], [%1], 16;" :: "r"(s), "l"(g));
}
#define CP_COMMIT() asm volatile("cp.async.commit_group;" ::: "memory")
#define CP_WAIT(N)  asm volatile("cp.async.wait_group %0;" :: "n"(N) : "memory")

// smem layout (bytes) -- 64 edges per CTA
#define SM_A     0        // 64x185 f32 A-coeffs (x staging 64x128 f32 first) = 47360
#define SM_HHI   47360    // 64x136 fp16 = 17408 (pitch 272 B)
#define SM_HLO   64768    // x lo (fc1 only) = 17408
#define SM_W     82176    // 3 x 34816 = 104448 (slot0 doubles as fc1 buffer)
#define SM_F2B   186624   // 1664 f32 = 6656
#define SM_F1B   193280   // 128 f32 = 512
#define SM_TOTAL 193792

#define THREADS  512
#define CHUNK_B  34816    // one fc2 chunk: 128 rows x 136 fp16 cols
#define APITCH   185

// ---------------------------------------------------------------------------
__global__ void prep_zero_kernel() {
    int i = blockIdx.x * 1024 + threadIdx.x;
    if (i < NNODE * DIRR) g_sums[i] = 0.f;
    else if (i < NNODE * DIRR + NNODE) g_cnt[i - NNODE * DIRR] = 0.f;
}

__global__ __launch_bounds__(256) void prep_proj_kernel(
        const float* __restrict__ node, const float* __restrict__ w,
        const float* __restrict__ b,    const float* __restrict__ l1) {
    __shared__ float sw[DNODE * M0_];
    __shared__ float sx[16 * DNODE];
    int tid = threadIdx.x, n0 = blockIdx.x * 16;
    for (int i = tid; i < DNODE * M0_; i += 256) sw[i] = w[i];
    for (int i = tid; i < 16 * DNODE; i += 256) sx[i] = node[n0 * DNODE + i];
    __syncthreads();
    int warp = tid >> 5, lane = tid & 31;
    for (int r = 0; r < 2; ++r) {
        int nl = warp * 2 + r;
        float acc = b[lane];
        const float* x = sx + nl * DNODE;
#pragma unroll 8
        for (int k = 0; k < DNODE; ++k) acc += x[k] * sw[k * M0_ + lane];
        g_feats[(n0 + nl) * DIRR + lane] = acc;
    }
    for (int i = tid; i < 16 * 24; i += 256) {
        int nl = i / 24, m = i - nl * 24;
        g_feats[(n0 + nl) * DIRR + M0_ + m] = l1[(n0 + nl) * 24 + m];
    }
}

// fc2 column permutation: chunk c, band wn (0..3), tile t (0..3), slot s (0..7)
__host__ __device__ __forceinline__ int perm_k(int c, int wn, int t, int s) {
    if (c < 8)  return (c * 4 + t) * 32 + wn * 8 + s;                    // W1
    if (c < 10) return 1024 + ((c - 8) * 16 + t * 4 + (s >> 1)) * 8      // W2
                       + wn * 2 + (s & 1);
    if (c < 12) return 1344 + ((c - 10) * 4 + t) * 32 + wn * 8 + s;      // W4
    if (t < 2)  return 1280 + (t * 4 + (s >> 1)) * 8 + wn * 2 + (s & 1); // W3
    return 1600 + ((t - 2) * 4 + (s >> 1)) * 8 + wn * 2 + (s & 1);       // W5
}

__global__ void prep_wsplit_kernel(const float* __restrict__ f1w,
                                   const float* __restrict__ f2w) {
    int i = blockIdx.x * 256 + threadIdx.x;
    if (i < 128 * 136) {
        int k = i / 136, n = i - k * 136;
        float v = (n < 128) ? f1w[k * 128 + n] : 0.f;
        ((__half*)g_w1)[i] = __float2half_rn(v);
    } else {
        int j = i - 128 * 136;
        if (j < 13 * 128 * 136) {
            int c = j / (128 * 136), r = j - c * (128 * 136);
            int krow = r / 136, col = r - krow * 136;
            float v = 0.f;
            if (col < 128) {
                int wn = col >> 5, t = (col >> 3) & 3, s = col & 7;
                v = f2w[(size_t)krow * WNUM_ + perm_k(c, wn, t, s)];
            }
            ((__half*)g_w2)[(size_t)c * 17408 + krow * 136 + col] =
                __float2half_rn(v);
        }
    }
}

// ---------------------------------------------------------------------------
__launch_bounds__(THREADS, 1) __global__
void e3_main_kernel(const float* __restrict__ pair,
                    const int*   __restrict__ pidx,
                    const float* __restrict__ esh,
                    const int*   __restrict__ esrc,
                    const int*   __restrict__ edst,
                    const float* __restrict__ lng,
                    const float* __restrict__ lnb,
                    const float* __restrict__ f1b,
                    const float* __restrict__ f2b) {
    extern __shared__ char smem[];
    float* sA     = (float*)(smem + SM_A);
    float* f2b_s  = (float*)(smem + SM_F2B);
    float* f1b_s  = (float*)(smem + SM_F1B);
    const uint32_t smW   = smem_u32(smem + SM_W);
    const uint32_t smHHI = smem_u32(smem + SM_HHI);
    const uint32_t smHLO = smem_u32(smem + SM_HLO);

    const int tid = threadIdx.x, warp = tid >> 5, lane = tid & 31;
    const int eb0 = blockIdx.x * 64;
    const int warp_m = warp & 3, wn = warp >> 2;       // 4m x 4n
    const int gr = lane >> 2, tig = lane & 3;
    const int e0l = warp_m * 16 + gr, e1l = e0l + 8;

    // ---- issue cp.async for fc1 weights into slot 0 -------------------------
#pragma unroll
    for (int u = 0; u < 5; ++u) {
        int idx = tid + u * THREADS;
        if (idx < 2176) cpasync16(smW + idx * 16, (const char*)g_w1 + idx * 16);
    }
    CP_COMMIT();

    // ---- gather x into sA [64][128] f32; copy biases -----------------------
    for (int idx4 = tid; idx4 < 64 * 32; idx4 += THREADS) {
        int el = idx4 >> 5, c4 = idx4 & 31;
        int e = eb0 + el;
        int b = pidx[e], i = pidx[NE + e], j = pidx[2 * NE + e];
        ((float4*)sA)[el * 32 + c4] =
            ((const float4*)(pair + (size_t)(((b * L_) + i) * L_ + j) * DPAIR))[c4];
    }
    for (int i4 = tid; i4 < WNUM_ / 4; i4 += THREADS)
        ((float4*)f2b_s)[i4] = ((const float4*)f2b)[i4];
    if (tid < 128) f1b_s[tid] = f1b[tid];
    __syncthreads();

    // ---- LayerNorm; write split x to hHi/hLo (warp: 4 edges) ---------------
    {
        float g0 = lng[lane], g1 = lng[lane + 32], g2 = lng[lane + 64], g3 = lng[lane + 96];
        float b0 = lnb[lane], b1 = lnb[lane + 32], b2 = lnb[lane + 64], b3 = lnb[lane + 96];
        for (int ee = 0; ee < 4; ++ee) {
            int el = warp * 4 + ee;
            const float* xr = sA + el * 128;
            float x0 = xr[lane], x1 = xr[lane + 32], x2 = xr[lane + 64], x3 = xr[lane + 96];
            float s = x0 + x1 + x2 + x3;
#pragma unroll
            for (int o = 16; o > 0; o >>= 1) s += __shfl_xor_sync(0xffffffffu, s, o);
            float mu = s * (1.f / 128.f);
            float d0 = x0 - mu, d1 = x1 - mu, d2 = x2 - mu, d3 = x3 - mu;
            float q = d0 * d0 + d1 * d1 + d2 * d2 + d3 * d3;
#pragma unroll
            for (int o = 16; o > 0; o >>= 1) q += __shfl_xor_sync(0xffffffffu, q, o);
            float rstd = rsqrtf(q * (1.f / 128.f) + 1e-5f);
            float v[4] = {d0 * rstd * g0 + b0, d1 * rstd * g1 + b1,
                          d2 * rstd * g2 + b2, d3 * rstd * g3 + b3};
#pragma unroll
            for (int p = 0; p < 4; ++p) {
                int col = lane + p * 32;
                __half h = __float2half_rn(v[p]);
                __half l = __float2half_rn(v[p] - __half2float(h));
                *(__half*)(smem + SM_HHI + el * 272 + col * 2) = h;
                *(__half*)(smem + SM_HLO + el * 272 + col * 2) = l;
            }
        }
    }
    __syncthreads();

    // ---- A-operand fragment preload (x hi/lo) -------------------------------
    uint32_t xh[8][4], xl[8][4];
    {
        int rowsel = warp_m * 16 + (lane & 15);
        uint32_t cextra = (lane & 16) ? 16 : 0;
#pragma unroll
        for (int ks = 0; ks < 8; ++ks) {
            uint32_t off = rowsel * 272 + ks * 32 + cextra;
            ldsm_x4(xh[ks], smHHI + off);
            ldsm_x4(xl[ks], smHLO + off);
        }
    }
    CP_WAIT(0);
    __syncthreads();

    // ---- fc1 MMA: h = relu(x @ fc1_w + b), 2-term fp16, bias in acc --------
#pragma unroll
    for (int t = 0; t < 4; ++t) {
        int colb = wn * 32 + t * 8 + 2 * tig;
        float2 bv = *(const float2*)&f1b_s[colb];
        float accE[4] = {bv.x, bv.y, bv.x, bv.y};
        float accO[4] = {0.f, 0.f, 0.f, 0.f};
        uint32_t col2 = (wn * 32 + t * 8) * 2;
#pragma unroll
        for (int kp = 0; kp < 4; ++kp) {
            float* acc = (kp & 1) ? accO : accE;
            uint32_t b4[4];
            ldsm_x4t(b4, smW + (kp * 32 + lane) * 272 + col2);
            mma_f16(acc, xh[2 * kp],     b4[0], b4[1]);
            mma_f16(acc, xh[2 * kp + 1], b4[2], b4[3]);
            mma_f16(acc, xl[2 * kp],     b4[0], b4[1]);
            mma_f16(acc, xl[2 * kp + 1], b4[2], b4[3]);
        }
#pragma unroll
        for (int e = 0; e < 2; ++e) {
            int row = warp_m * 16 + gr + e * 8;
            float v0 = fmaxf(accE[2 * e]     + accO[2 * e],     0.f);
            float v1 = fmaxf(accE[2 * e + 1] + accO[2 * e + 1], 0.f);
            __half h0 = __float2half_rn(v0), h1 = __float2half_rn(v1);
            *(__half2*)(smem + SM_HHI + row * 272 + colb * 2) =
                __halves2half2(h0, h1);
        }
    }
    __syncthreads();   // all warps done reading fc1 w (slot0) + writing h

    // ---- prefetch fc2 chunks 0 and 1 ---------------------------------------
#pragma unroll
    for (int u = 0; u < 5; ++u) {
        int idx = tid + u * THREADS;
        if (idx < 2176) cpasync16(smW + idx * 16, (const char*)g_w2 + idx * 16);
    }
    CP_COMMIT();
#pragma unroll
    for (int u = 0; u < 5; ++u) {
        int idx = tid + u * THREADS;
        if (idx < 2176)
            cpasync16(smW + CHUNK_B + idx * 16,
                      (const char*)g_w2 + CHUNK_B + idx * 16);
    }
    CP_COMMIT();

    // ---- A coefficients: warp handles 4 edges, lane-strided -----------------
#pragma unroll 1
    for (int ee = 0; ee < 4; ++ee) {
        int el = warp * 4 + ee;
        int e  = eb0 + el;
        const float* F  = g_feats + edst[e] * DIRR;
        const float* SH = esh + e * 9;
        float* Adst = sA + el * APITCH;
        for (int a = lane; a < 184; a += 32) {
            float val;
            if (a < 32) {
                val = PW0 * F[a] * SH[0];
            } else if (a < 40) {
                int u = a - 32;
                val = (PW0 * S3C) * (F[32 + u * 3] * SH[1] + F[33 + u * 3] * SH[2]
                                     + F[34 + u * 3] * SH[3]);
            } else if (a < 136) {
                int t = a - 40; int u = t / 3, m = t - u * 3;
                val = (PW1 * S3C) * F[u] * SH[1 + m];
            } else if (a < 160) {
                int t = a - 136; int u = t / 3, m = t - u * 3;
                val = (PW1 * S3C) * F[32 + u * 3 + m] * SH[0];
            } else {
                int t = a - 160; int u = t / 3, m = t - u * 3;
                float xx = F[32 + u * 3], xy = F[33 + u * 3], xz = F[34 + u * 3];
                float s0 = SH[4], s1 = SH[5], s2 = SH[6], s3v = SH[7], s4 = SH[8];
                float t5;
                if (m == 0)      t5 = (xz * s0 + xy * s1 - xx * s4) * S3C - xx * s2 * (1.f / 3.f);
                else if (m == 1) t5 = (xx * s1 + xz * s3v) * S3C + xy * s2 * (2.f / 3.f);
                else             t5 = (xx * s0 + xy * s3v + xz * s4) * S3C - xz * s2 * (1.f / 3.f);
                val = (PW1 * F121) * t5;
            }
            Adst[a] = val;
        }
    }
    __syncthreads();   // h + A complete

    // ---- reload A-operand fragments (h hi only) ------------------------------
    {
        int rowsel = warp_m * 16 + (lane & 15);
        uint32_t cextra = (lane & 16) ? 16 : 0;
#pragma unroll
        for (int ks = 0; ks < 8; ++ks)
            ldsm_x4(xh[ks], smHHI + rowsel * 272 + ks * 32 + cextra);
    }

    // ---- fc2 chunk loop (13 chunks, fully unrolled, compile-time decode) ----
    float conv0[4]  = {0.f, 0.f, 0.f, 0.f};
    float conv1[12];
#pragma unroll
    for (int o = 0; o < 12; ++o) conv1[o] = 0.f;
    const float* Arow0 = sA + e0l * APITCH;
    const float* Arow1 = sA + e1l * APITCH;

#pragma unroll
    for (int c = 0; c < 13; ++c) {
        if (c < 12) { CP_WAIT(1); } else { CP_WAIT(0); }
        __syncthreads();

        if (c + 2 < 13) {
            const char* gsrc = (const char*)g_w2 + (size_t)(c + 2) * CHUNK_B;
            uint32_t sdst = smW + (uint32_t)(((c + 2) % 3) * CHUNK_B);
#pragma unroll
            for (int u = 0; u < 5; ++u) {
                int idx = tid + u * THREADS;
                if (idx < 2176) cpasync16(sdst + idx * 16, gsrc + idx * 16);
            }
            CP_COMMIT();
        }

        const uint32_t buf = smW + (uint32_t)((c % 3) * CHUNK_B);
#pragma unroll
        for (int tp = 0; tp < 2; ++tp) {
            // batch-load B fragments for tile pair
            uint32_t Bf[2][4][4];
#pragma unroll
            for (int tt = 0; tt < 2; ++tt) {
                uint32_t col2 = (wn * 32 + (tp * 2 + tt) * 8) * 2;
#pragma unroll
                for (int kp = 0; kp < 4; ++kp)
                    ldsm_x4t(Bf[tt][kp], buf + (kp * 32 + lane) * 272 + col2);
            }
#pragma unroll
            for (int tt = 0; tt < 2; ++tt) {
                const int t = tp * 2 + tt;
                // compile-time region decode
                const bool isC0 = (c < 8) || (c >= 10 && c < 12);
                float accE[4], accO[4] = {0.f, 0.f, 0.f, 0.f};
                if (isC0) {
                    const int kb = (c < 8) ? ((c * 4 + t) * 32)
                                           : (1344 + ((c - 10) * 4 + t) * 32);
                    float2 bv = *(const float2*)&f2b_s[kb + wn * 8 + 2 * tig];
                    accE[0] = bv.x; accE[1] = bv.y; accE[2] = bv.x; accE[3] = bv.y;
                } else {
                    const int kbb = (c < 10) ? (1024 + ((c - 8) * 16 + t * 4) * 8)
                                  : ((t < 2) ? (1280 + (t * 4) * 8)
                                             : (1600 + ((t - 2) * 4) * 8));
                    float2 bv = *(const float2*)&f2b_s[kbb + tig * 8 + wn * 2];
                    accE[0] = bv.x; accE[1] = bv.y; accE[2] = bv.x; accE[3] = bv.y;
                }
                mma_f16(accE, xh[0], Bf[tt][0][0], Bf[tt][0][1]);
                mma_f16(accO, xh[1], Bf[tt][0][2], Bf[tt][0][3]);
                mma_f16(accE, xh[2], Bf[tt][1][0], Bf[tt][1][1]);
                mma_f16(accO, xh[3], Bf[tt][1][2], Bf[tt][1][3]);
                mma_f16(accE, xh[4], Bf[tt][2][0], Bf[tt][2][1]);
                mma_f16(accO, xh[5], Bf[tt][2][2], Bf[tt][2][3]);
                mma_f16(accE, xh[6], Bf[tt][3][0], Bf[tt][3][1]);
                mma_f16(accO, xh[7], Bf[tt][3][2], Bf[tt][3][3]);
                float acc[4];
#pragma unroll
                for (int q = 0; q < 4; ++q) acc[q] = accE[q] + accO[q];

                if (isC0) {
                    const int u = (c < 8) ? (c * 4 + t) : (32 + (c - 10) * 4 + t);
                    float a0 = Arow0[u], a1 = Arow1[u];
                    conv0[0] += a0 * acc[0];
                    conv0[1] += a0 * acc[1];
                    conv0[2] += a1 * acc[2];
                    conv0[3] += a1 * acc[3];
                } else {
                    const int base = (c < 10) ? 40 : ((t < 2) ? 136 : 160);
                    const int ub   = (c < 10) ? ((c - 8) * 16 + t * 4)
                                   : ((t < 2) ? (t * 4) : ((t - 2) * 4));
                    const float* A0 = Arow0 + base + (ub + tig) * 3;
                    const float* A1 = Arow1 + base + (ub + tig) * 3;
#pragma unroll
                    for (int m = 0; m < 3; ++m) {
                        conv1[m]     += A0[m] * acc[0];
                        conv1[3 + m] += A0[m] * acc[1];
                        conv1[6 + m] += A1[m] * acc[2];
                        conv1[9 + m] += A1[m] * acc[3];
                    }
                }
            }
        }
    }

    // ---- conv1: reduce across tig (lanes xor 1,2), then scatter -------------
#pragma unroll
    for (int o = 0; o < 12; ++o) {
        conv1[o] += __shfl_xor_sync(0xffffffffu, conv1[o], 1);
        conv1[o] += __shfl_xor_sync(0xffffffffu, conv1[o], 2);
    }

    {
        int s0 = esrc[eb0 + e0l] * DIRR;
        int s1 = esrc[eb0 + e1l] * DIRR;
#pragma unroll
        for (int j = 0; j < 2; ++j) {
            int v = wn * 8 + 2 * tig + j;
            atomicAdd(&g_sums[s0 + v], conv0[j]);
            atomicAdd(&g_sums[s1 + v], conv0[2 + j]);
        }
        if (tig == 0) {
#pragma unroll
            for (int j = 0; j < 2; ++j)
#pragma unroll
                for (int m = 0; m < 3; ++m) {
                    int o = 32 + (wn * 2 + j) * 3 + m;
                    atomicAdd(&g_sums[s0 + o], conv1[j * 3 + m]);
                    atomicAdd(&g_sums[s1 + o], conv1[6 + j * 3 + m]);
                }
        }
    }
    if (tid < 64) atomicAdd(&g_cnt[esrc[eb0 + tid]], 1.f);
}

// ---------------------------------------------------------------------------
__global__ void finalize_kernel(const float* __restrict__ node,
                                const float* __restrict__ l1,
                                const float* __restrict__ pnw,
                                const float* __restrict__ pnb,
                                float* __restrict__ out) {
    int n = blockIdx.x;
    __shared__ float o0[32];
    float inv = 1.f / fmaxf(g_cnt[n], 1.f);
    if (threadIdx.x < 32) o0[threadIdx.x] = g_sums[n * DIRR + threadIdx.x] * inv;
    __syncthreads();
    int d = threadIdx.x;
    float acc = pnb[d];
#pragma unroll
    for (int u = 0; u < 32; ++u) acc += o0[u] * pnw[u * DNODE + d];
    out[n * DNODE + d] = acc + node[n * DNODE + d];
    if (d < 24)
        out[NNODE * DNODE + n * 24 + d] = g_sums[n * DIRR + 32 + d] * inv + l1[n * 24 + d];
}

// ---------------------------------------------------------------------------
extern "C" void kernel_launch(void* const* d_in, const int* in_sizes, int n_in,
                              void* d_out, int out_size) {
    const float* node = (const float*)d_in[0];
    const float* pair = (const float*)d_in[1];
    const float* l1   = (const float*)d_in[2];
    const float* esh  = (const float*)d_in[3];
    const float* pl0w = (const float*)d_in[4];
    const float* pl0b = (const float*)d_in[5];
    const float* pnw  = (const float*)d_in[6];
    const float* pnb  = (const float*)d_in[7];
    const float* lng  = (const float*)d_in[8];
    const float* lnb  = (const float*)d_in[9];
    const float* f1w  = (const float*)d_in[10];
    const float* f1b  = (const float*)d_in[11];
    const float* f2w  = (const float*)d_in[12];
    const float* f2b  = (const float*)d_in[13];
    const int*   pidx = (const int*)d_in[14];
    const int*   esrc = (const int*)d_in[15];
    const int*   edst = (const int*)d_in[16];
    float* out = (float*)d_out;

    cudaFuncSetAttribute(e3_main_kernel,
                         cudaFuncAttributeMaxDynamicSharedMemorySize, SM_TOTAL);

    prep_zero_kernel<<<57, 1024>>>();
    prep_proj_kernel<<<64, 256>>>(node, pl0w, pl0b, l1);
    prep_wsplit_kernel<<<952, 256>>>(f1w, f2w);
    e3_main_kernel<<<NE / 64, THREADS, SM_TOTAL>>>(pair, pidx, esh, esrc, edst,
                                                   lng, lnb, f1b, f2b);
    finalize_kernel<<<NNODE, 256>>>(node, l1, pnw, pnb, out);
}

// round 12
// speedup vs baseline: 6.1844x; 1.0183x over previous
#include <cuda_runtime.h>
#include <cuda_fp16.h>
#include <cstdint>

#define B_     4
#define L_     256
#define NNODE  1024
#define DNODE  256
#define DPAIR  128
#define NE     65536
#define M0_    32
#define DIRR   56
#define WNUM_  1664

#define PW0   0.15811388300841897f
#define PW1   0.25f
#define S3C   0.5773502691896258f
#define F121  0.5477225575051661f

// device scratch (no allocations allowed)
__device__ float g_feats[NNODE * DIRR];
__device__ float g_sums [NNODE * DIRR];
__device__ float g_cnt  [NNODE];
// pre-split weights (fp16), padded + column-permuted layouts
__device__ uint4 g_w1[2176];     // fc1: 128 x 136 fp16 = 34,816 B
__device__ uint4 g_w2[28288];    // fc2: 13 chunks x 128 x 136 fp16 = 452,608 B

// ---------------- plain-PTX helpers (sm_80-level, safe on sm_103) ----------
__device__ __forceinline__ uint32_t smem_u32(const void* p) {
    uint32_t a;
    asm("{ .reg .u64 t; cvta.to.shared.u64 t, %1; cvt.u32.u64 %0, t; }"
        : "=r"(a) : "l"(p));
    return a;
}
__device__ __forceinline__ void ldsm_x4(uint32_t* r, uint32_t addr) {
    asm volatile("ldmatrix.sync.aligned.m8n8.x4.shared.b16 {%0,%1,%2,%3}, [%4];"
        : "=r"(r[0]), "=r"(r[1]), "=r"(r[2]), "=r"(r[3]) : "r"(addr));
}
__device__ __forceinline__ void ldsm_x4t(uint32_t* r, uint32_t addr) {
    asm volatile("ldmatrix.sync.aligned.m8n8.x4.trans.shared.b16 {%0,%1,%2,%3}, [%4];"
        : "=r"(r[0]), "=r"(r[1]), "=r"(r[2]), "=r"(r[3]) : "r"(addr));
}
__device__ __forceinline__ void mma_f16(float* d, const uint32_t* a,
                                        uint32_t b0, uint32_t b1) {
    asm volatile("mma.sync.aligned.m16n8k16.row.col.f32.f16.f16.f32 "
        "{%0,%1,%2,%3}, {%4,%5,%6,%7}, {%8,%9}, {%0,%1,%2,%3};"
        : "+f"(d[0]), "+f"(d[1]), "+f"(d[2]), "+f"(d[3])
        : "r"(a[0]), "r"(a[1]), "r"(a[2]), "r"(a[3]), "r"(b0), "r"(b1));
}
__device__ __forceinline__ void cpasync16(uint32_t s, const void* g) {
    asm volatile("cp.async.cg.shared.global [%0], [%1], 16;" :: "r"(s), "l"(g));
}
#define CP_COMMIT() asm volatile("cp.async.commit_group;" ::: "memory")
#define CP_WAIT(N)  asm volatile("cp.async.wait_group %0;" :: "n"(N) : "memory")

// smem layout (bytes) -- 128 edges per CTA
#define CHUNK_B  34816    // one fc2 chunk: 128 rows x 136 fp16 cols
#define SM_W     0        // 2 slots: slot0 fc1w->chunks, slot1 xlo->chunks
#define SM_XLO   34816    // = slot1
#define SM_HHI   69632    // 128x136 fp16, pitch 272 B
#define SM_A     104448   // x staging (128x128 f32 = 65536) then A coeffs 128x185 f32
#define SM_F2B   199168   // 1664 f32
#define SM_F1B   205824   // 128 f32
#define SM_TOTAL 206336

#define THREADS  512
#define APITCH   185

// ---------------------------------------------------------------------------
__global__ void prep_zero_kernel() {
    int i = blockIdx.x * 1024 + threadIdx.x;
    if (i < NNODE * DIRR) g_sums[i] = 0.f;
    else if (i < NNODE * DIRR + NNODE) g_cnt[i - NNODE * DIRR] = 0.f;
}

__global__ __launch_bounds__(256) void prep_proj_kernel(
        const float* __restrict__ node, const float* __restrict__ w,
        const float* __restrict__ b,    const float* __restrict__ l1) {
    __shared__ float sw[DNODE * M0_];
    __shared__ float sx[16 * DNODE];
    int tid = threadIdx.x, n0 = blockIdx.x * 16;
    for (int i = tid; i < DNODE * M0_; i += 256) sw[i] = w[i];
    for (int i = tid; i < 16 * DNODE; i += 256) sx[i] = node[n0 * DNODE + i];
    __syncthreads();
    int warp = tid >> 5, lane = tid & 31;
    for (int r = 0; r < 2; ++r) {
        int nl = warp * 2 + r;
        float acc = b[lane];
        const float* x = sx + nl * DNODE;
#pragma unroll 8
        for (int k = 0; k < DNODE; ++k) acc += x[k] * sw[k * M0_ + lane];
        g_feats[(n0 + nl) * DIRR + lane] = acc;
    }
    for (int i = tid; i < 16 * 24; i += 256) {
        int nl = i / 24, m = i - nl * 24;
        g_feats[(n0 + nl) * DIRR + M0_ + m] = l1[(n0 + nl) * 24 + m];
    }
}

// fc2 column permutation: chunk c, band wn (0..3), tile t (0..3), slot s (0..7)
__host__ __device__ __forceinline__ int perm_k(int c, int wn, int t, int s) {
    if (c < 8)  return (c * 4 + t) * 32 + wn * 8 + s;                    // W1
    if (c < 10) return 1024 + ((c - 8) * 16 + t * 4 + (s >> 1)) * 8      // W2
                       + wn * 2 + (s & 1);
    if (c < 12) return 1344 + ((c - 10) * 4 + t) * 32 + wn * 8 + s;      // W4
    if (t < 2)  return 1280 + (t * 4 + (s >> 1)) * 8 + wn * 2 + (s & 1); // W3
    return 1600 + ((t - 2) * 4 + (s >> 1)) * 8 + wn * 2 + (s & 1);       // W5
}

__global__ void prep_wsplit_kernel(const float* __restrict__ f1w,
                                   const float* __restrict__ f2w) {
    int i = blockIdx.x * 256 + threadIdx.x;
    if (i < 128 * 136) {
        int k = i / 136, n = i - k * 136;
        float v = (n < 128) ? f1w[k * 128 + n] : 0.f;
        ((__half*)g_w1)[i] = __float2half_rn(v);
    } else {
        int j = i - 128 * 136;
        if (j < 13 * 128 * 136) {
            int c = j / (128 * 136), r = j - c * (128 * 136);
            int krow = r / 136, col = r - krow * 136;
            float v = 0.f;
            if (col < 128) {
                int wn = col >> 5, t = (col >> 3) & 3, s = col & 7;
                v = f2w[(size_t)krow * WNUM_ + perm_k(c, wn, t, s)];
            }
            ((__half*)g_w2)[(size_t)c * 17408 + krow * 136 + col] =
                __float2half_rn(v);
        }
    }
}

// ---------------------------------------------------------------------------
__launch_bounds__(THREADS, 1) __global__
void e3_main_kernel(const float* __restrict__ pair,
                    const int*   __restrict__ pidx,
                    const float* __restrict__ esh,
                    const int*   __restrict__ esrc,
                    const int*   __restrict__ edst,
                    const float* __restrict__ lng,
                    const float* __restrict__ lnb,
                    const float* __restrict__ f1b,
                    const float* __restrict__ f2b) {
    extern __shared__ char smem[];
    float* sA     = (float*)(smem + SM_A);
    float* f2b_s  = (float*)(smem + SM_F2B);
    float* f1b_s  = (float*)(smem + SM_F1B);
    const uint32_t smW   = smem_u32(smem + SM_W);
    const uint32_t smXLO = smW + CHUNK_B;
    const uint32_t smHHI = smem_u32(smem + SM_HHI);

    const int tid = threadIdx.x, warp = tid >> 5, lane = tid & 31;
    const int eb0 = blockIdx.x * 128;
    const int warp_m = warp & 3, wn = warp >> 2;       // 4m x 4n
    const int gr = lane >> 2, tig = lane & 3;
    const int eB = warp_m * 16 + gr;                   // base edge (mt0, row gr)

    // ---- issue cp.async for fc1 weights into slot 0 -------------------------
#pragma unroll
    for (int u = 0; u < 5; ++u) {
        int idx = tid + u * THREADS;
        if (idx < 2176) cpasync16(smW + idx * 16, (const char*)g_w1 + idx * 16);
    }
    CP_COMMIT();

    // ---- gather x into sA [128][128] f32; copy biases ----------------------
    for (int idx4 = tid; idx4 < 128 * 32; idx4 += THREADS) {
        int el = idx4 >> 5, c4 = idx4 & 31;
        int e = eb0 + el;
        int b = pidx[e], i = pidx[NE + e], j = pidx[2 * NE + e];
        ((float4*)sA)[el * 32 + c4] =
            ((const float4*)(pair + (size_t)(((b * L_) + i) * L_ + j) * DPAIR))[c4];
    }
    for (int i4 = tid; i4 < WNUM_ / 4; i4 += THREADS)
        ((float4*)f2b_s)[i4] = ((const float4*)f2b)[i4];
    if (tid < 128) f1b_s[tid] = f1b[tid];
    __syncthreads();

    // ---- LayerNorm; write split x to HHI / XLO (warp: 8 edges) -------------
    {
        float g0 = lng[lane], g1 = lng[lane + 32], g2 = lng[lane + 64], g3 = lng[lane + 96];
        float b0 = lnb[lane], b1 = lnb[lane + 32], b2 = lnb[lane + 64], b3 = lnb[lane + 96];
        for (int ee = 0; ee < 8; ++ee) {
            int el = warp * 8 + ee;
            const float* xr = sA + el * 128;
            float x0 = xr[lane], x1 = xr[lane + 32], x2 = xr[lane + 64], x3 = xr[lane + 96];
            float s = x0 + x1 + x2 + x3;
#pragma unroll
            for (int o = 16; o > 0; o >>= 1) s += __shfl_xor_sync(0xffffffffu, s, o);
            float mu = s * (1.f / 128.f);
            float d0 = x0 - mu, d1 = x1 - mu, d2 = x2 - mu, d3 = x3 - mu;
            float q = d0 * d0 + d1 * d1 + d2 * d2 + d3 * d3;
#pragma unroll
            for (int o = 16; o > 0; o >>= 1) q += __shfl_xor_sync(0xffffffffu, q, o);
            float rstd = rsqrtf(q * (1.f / 128.f) + 1e-5f);
            float v[4] = {d0 * rstd * g0 + b0, d1 * rstd * g1 + b1,
                          d2 * rstd * g2 + b2, d3 * rstd * g3 + b3};
#pragma unroll
            for (int p = 0; p < 4; ++p) {
                int col = lane + p * 32;
                __half h = __float2half_rn(v[p]);
                __half l = __float2half_rn(v[p] - __half2float(h));
                *(__half*)(smem + SM_HHI + el * 272 + col * 2) = h;
                *(__half*)(smem + SM_XLO + el * 272 + col * 2) = l;
            }
        }
    }
    __syncthreads();
    CP_WAIT(0);     // fc1 weights resident

    // ---- fc1: two sequential m-halves; h = relu(x @ fc1_w + b) -------------
#pragma unroll 1
    for (int hh = 0; hh < 2; ++hh) {
        const int hr = hh * 64 + warp_m * 16;
        uint32_t xa[8][4], xb[8][4];
        {
            int rowsel = hr + (lane & 15);
            uint32_t cex = (lane & 16) ? 16 : 0;
#pragma unroll
            for (int ks = 0; ks < 8; ++ks) {
                uint32_t off = rowsel * 272 + ks * 32 + cex;
                ldsm_x4(xa[ks], smHHI + off);
                ldsm_x4(xb[ks], smXLO + off);
            }
        }
        __syncthreads();   // all reads of this half's rows done before stores
#pragma unroll
        for (int t = 0; t < 4; ++t) {
            int colb = wn * 32 + t * 8 + 2 * tig;
            float2 bv = *(const float2*)&f1b_s[colb];
            float accE[4] = {bv.x, bv.y, bv.x, bv.y};
            float accO[4] = {0.f, 0.f, 0.f, 0.f};
            uint32_t col2 = (wn * 32 + t * 8) * 2;
#pragma unroll
            for (int kp = 0; kp < 4; ++kp) {
                uint32_t b4[4];
                ldsm_x4t(b4, smW + (kp * 32 + lane) * 272 + col2);
                mma_f16(accE, xa[2 * kp],     b4[0], b4[1]);
                mma_f16(accO, xa[2 * kp + 1], b4[2], b4[3]);
                mma_f16(accE, xb[2 * kp],     b4[0], b4[1]);
                mma_f16(accO, xb[2 * kp + 1], b4[2], b4[3]);
            }
#pragma unroll
            for (int e = 0; e < 2; ++e) {
                int row = hr + gr + e * 8;
                float v0 = fmaxf(accE[2 * e]     + accO[2 * e],     0.f);
                float v1 = fmaxf(accE[2 * e + 1] + accO[2 * e + 1], 0.f);
                *(__half2*)(smem + SM_HHI + row * 272 + colb * 2) =
                    __halves2half2(__float2half_rn(v0), __float2half_rn(v1));
            }
        }
    }
    __syncthreads();   // fc1 done: slot0 + XLO free, h complete

    // ---- prefetch fc2 chunks 0 (slot0) and 1 (slot1) ------------------------
#pragma unroll
    for (int u = 0; u < 5; ++u) {
        int idx = tid + u * THREADS;
        if (idx < 2176) cpasync16(smW + idx * 16, (const char*)g_w2 + idx * 16);
    }
    CP_COMMIT();
#pragma unroll
    for (int u = 0; u < 5; ++u) {
        int idx = tid + u * THREADS;
        if (idx < 2176)
            cpasync16(smW + CHUNK_B + idx * 16,
                      (const char*)g_w2 + CHUNK_B + idx * 16);
    }
    CP_COMMIT();

    // ---- A coefficients over dead x (warp: 8 edges, lane-strided) -----------
#pragma unroll 1
    for (int ee = 0; ee < 8; ++ee) {
        int el = warp * 8 + ee;
        int e  = eb0 + el;
        const float* F  = g_feats + edst[e] * DIRR;
        const float* SH = esh + e * 9;
        float* Adst = sA + el * APITCH;
        for (int a = lane; a < 184; a += 32) {
            float val;
            if (a < 32) {
                val = PW0 * F[a] * SH[0];
            } else if (a < 40) {
                int u = a - 32;
                val = (PW0 * S3C) * (F[32 + u * 3] * SH[1] + F[33 + u * 3] * SH[2]
                                     + F[34 + u * 3] * SH[3]);
            } else if (a < 136) {
                int t = a - 40; int u = t / 3, m = t - u * 3;
                val = (PW1 * S3C) * F[u] * SH[1 + m];
            } else if (a < 160) {
                int t = a - 136; int u = t / 3, m = t - u * 3;
                val = (PW1 * S3C) * F[32 + u * 3 + m] * SH[0];
            } else {
                int t = a - 160; int u = t / 3, m = t - u * 3;
                float xx = F[32 + u * 3], xy = F[33 + u * 3], xz = F[34 + u * 3];
                float s0 = SH[4], s1 = SH[5], s2 = SH[6], s3v = SH[7], s4 = SH[8];
                float t5;
                if (m == 0)      t5 = (xz * s0 + xy * s1 - xx * s4) * S3C - xx * s2 * (1.f / 3.f);
                else if (m == 1) t5 = (xx * s1 + xz * s3v) * S3C + xy * s2 * (2.f / 3.f);
                else             t5 = (xx * s0 + xy * s3v + xz * s4) * S3C - xz * s2 * (1.f / 3.f);
                val = (PW1 * F121) * t5;
            }
            Adst[a] = val;
        }
    }

    // ---- load h fragments for BOTH m-tiles (reused across all 13 chunks) ----
    uint32_t xh[16][4];
    {
        int rowsel = warp_m * 16 + (lane & 15);
        uint32_t cex = (lane & 16) ? 16 : 0;
#pragma unroll
        for (int ks = 0; ks < 8; ++ks) {
            ldsm_x4(xh[ks],     smHHI + rowsel * 272 + ks * 32 + cex);
            ldsm_x4(xh[8 + ks], smHHI + (rowsel + 64) * 272 + ks * 32 + cex);
        }
    }
    __syncthreads();   // A complete; h fragment reads done

    // ---- fc2 chunk loop: 13 chunks, 2 m-tiles per warp, double-buffered -----
    float conv0[8];
#pragma unroll
    for (int o = 0; o < 8; ++o) conv0[o] = 0.f;
    float conv1[24];
#pragma unroll
    for (int o = 0; o < 24; ++o) conv1[o] = 0.f;
    const float* aB = sA + eB * APITCH;   // edge rows: +0, +8*185, +64*185, +72*185

#pragma unroll
    for (int c = 0; c < 13; ++c) {
        if (c < 12) { CP_WAIT(1); } else { CP_WAIT(0); }
        __syncthreads();

        const uint32_t buf = smW + (uint32_t)((c & 1) * CHUNK_B);
#pragma unroll
        for (int t = 0; t < 4; ++t) {
            const bool isC0 = (c < 8) || (c >= 10 && c < 12);
            float acc0[4], acc1[4];
            if (isC0) {
                const int kb = (c < 8) ? ((c * 4 + t) * 32)
                                       : (1344 + ((c - 10) * 4 + t) * 32);
                float2 bv = *(const float2*)&f2b_s[kb + wn * 8 + 2 * tig];
                acc0[0] = bv.x; acc0[1] = bv.y; acc0[2] = bv.x; acc0[3] = bv.y;
                acc1[0] = bv.x; acc1[1] = bv.y; acc1[2] = bv.x; acc1[3] = bv.y;
            } else {
                const int kbb = (c < 10) ? (1024 + ((c - 8) * 16 + t * 4) * 8)
                              : ((t < 2) ? (1280 + (t * 4) * 8)
                                         : (1600 + ((t - 2) * 4) * 8));
                float2 bv = *(const float2*)&f2b_s[kbb + tig * 8 + wn * 2];
                acc0[0] = bv.x; acc0[1] = bv.y; acc0[2] = bv.x; acc0[3] = bv.y;
                acc1[0] = bv.x; acc1[1] = bv.y; acc1[2] = bv.x; acc1[3] = bv.y;
            }
            uint32_t col2 = (wn * 32 + t * 8) * 2;
#pragma unroll
            for (int kp = 0; kp < 4; ++kp) {
                uint32_t b4[4];
                ldsm_x4t(b4, buf + (kp * 32 + lane) * 272 + col2);
                mma_f16(acc0, xh[2 * kp],         b4[0], b4[1]);
                mma_f16(acc1, xh[8 + 2 * kp],     b4[0], b4[1]);
                mma_f16(acc0, xh[2 * kp + 1],     b4[2], b4[3]);
                mma_f16(acc1, xh[8 + 2 * kp + 1], b4[2], b4[3]);
            }

            if (isC0) {
                const int u = (c < 8) ? (c * 4 + t) : (32 + (c - 10) * 4 + t);
                float a0 = aB[u];
                float a1 = aB[u + 8 * APITCH];
                float a2 = aB[u + 64 * APITCH];
                float a3 = aB[u + 72 * APITCH];
                conv0[0] += a0 * acc0[0]; conv0[1] += a0 * acc0[1];
                conv0[2] += a1 * acc0[2]; conv0[3] += a1 * acc0[3];
                conv0[4] += a2 * acc1[0]; conv0[5] += a2 * acc1[1];
                conv0[6] += a3 * acc1[2]; conv0[7] += a3 * acc1[3];
            } else {
                const int base = (c < 10) ? 40 : ((t < 2) ? 136 : 160);
                const int ub   = (c < 10) ? ((c - 8) * 16 + t * 4)
                               : ((t < 2) ? (t * 4) : ((t - 2) * 4));
                const int off  = base + ub * 3;
                const float* A0 = aB + off + tig * 3;
                const float* A1 = A0 + 8 * APITCH;
                const float* A2 = A0 + 64 * APITCH;
                const float* A3 = A0 + 72 * APITCH;
#pragma unroll
                for (int m = 0; m < 3; ++m) {
                    conv1[m]      += A0[m] * acc0[0];
                    conv1[3 + m]  += A0[m] * acc0[1];
                    conv1[6 + m]  += A1[m] * acc0[2];
                    conv1[9 + m]  += A1[m] * acc0[3];
                    conv1[12 + m] += A2[m] * acc1[0];
                    conv1[15 + m] += A2[m] * acc1[1];
                    conv1[18 + m] += A3[m] * acc1[2];
                    conv1[21 + m] += A3[m] * acc1[3];
                }
            }
        }

        __syncthreads();   // all warps done reading slot (c&1)
        if (c + 2 < 13) {
            const char* gsrc = (const char*)g_w2 + (size_t)(c + 2) * CHUNK_B;
            uint32_t sdst = smW + (uint32_t)((c & 1) * CHUNK_B);
#pragma unroll
            for (int u = 0; u < 5; ++u) {
                int idx = tid + u * THREADS;
                if (idx < 2176) cpasync16(sdst + idx * 16, gsrc + idx * 16);
            }
            CP_COMMIT();
        }
    }

    // ---- conv1: reduce across tig (lanes xor 1,2), then scatter -------------
#pragma unroll
    for (int o = 0; o < 24; ++o) {
        conv1[o] += __shfl_xor_sync(0xffffffffu, conv1[o], 1);
        conv1[o] += __shfl_xor_sync(0xffffffffu, conv1[o], 2);
    }

    {
        int s0 = esrc[eb0 + eB]      * DIRR;
        int s1 = esrc[eb0 + eB + 8]  * DIRR;
        int s2 = esrc[eb0 + eB + 64] * DIRR;
        int s3 = esrc[eb0 + eB + 72] * DIRR;
#pragma unroll
        for (int j = 0; j < 2; ++j) {
            int v = wn * 8 + 2 * tig + j;
            atomicAdd(&g_sums[s0 + v], conv0[j]);
            atomicAdd(&g_sums[s1 + v], conv0[2 + j]);
            atomicAdd(&g_sums[s2 + v], conv0[4 + j]);
            atomicAdd(&g_sums[s3 + v], conv0[6 + j]);
        }
        if (tig == 0) {
#pragma unroll
            for (int j = 0; j < 2; ++j)
#pragma unroll
                for (int m = 0; m < 3; ++m) {
                    int o = 32 + (wn * 2 + j) * 3 + m;
                    atomicAdd(&g_sums[s0 + o], conv1[j * 3 + m]);
                    atomicAdd(&g_sums[s1 + o], conv1[6 + j * 3 + m]);
                    atomicAdd(&g_sums[s2 + o], conv1[12 + j * 3 + m]);
                    atomicAdd(&g_sums[s3 + o], conv1[18 + j * 3 + m]);
                }
        }
    }
    if (tid < 128) atomicAdd(&g_cnt[esrc[eb0 + tid]], 1.f);
}

// ---------------------------------------------------------------------------
__global__ void finalize_kernel(const float* __restrict__ node,
                                const float* __restrict__ l1,
                                const float* __restrict__ pnw,
                                const float* __restrict__ pnb,
                                float* __restrict__ out) {
    int n = blockIdx.x;
    __shared__ float o0[32];
    float inv = 1.f / fmaxf(g_cnt[n], 1.f);
    if (threadIdx.x < 32) o0[threadIdx.x] = g_sums[n * DIRR + threadIdx.x] * inv;
    __syncthreads();
    int d = threadIdx.x;
    float acc = pnb[d];
#pragma unroll
    for (int u = 0; u < 32; ++u) acc += o0[u] * pnw[u * DNODE + d];
    out[n * DNODE + d] = acc + node[n * DNODE + d];
    if (d < 24)
        out[NNODE * DNODE + n * 24 + d] = g_sums[n * DIRR + 32 + d] * inv + l1[n * 24 + d];
}

// ---------------------------------------------------------------------------
extern "C" void kernel_launch(void* const* d_in, const int* in_sizes, int n_in,
                              void* d_out, int out_size) {
    const float* node = (const float*)d_in[0];
    const float* pair = (const float*)d_in[1];
    const float* l1   = (const float*)d_in[2];
    const float* esh  = (const float*)d_in[3];
    const float* pl0w = (const float*)d_in[4];
    const float* pl0b = (const float*)d_in[5];
    const float* pnw  = (const float*)d_in[6];
    const float* pnb  = (const float*)d_in[7];
    const float* lng  = (const float*)d_in[8];
    const float* lnb  = (const float*)d_in[9];
    const float* f1w  = (const float*)d_in[10];
    const float* f1b  = (const float*)d_in[11];
    const float* f2w  = (const float*)d_in[12];
    const float* f2b  = (const float*)d_in[13];
    const int*   pidx = (const int*)d_in[14];
    const int*   esrc = (const int*)d_in[15];
    const int*   edst = (const int*)d_in[16];
    float* out = (float*)d_out;

    cudaFuncSetAttribute(e3_main_kernel,
                         cudaFuncAttributeMaxDynamicSharedMemorySize, SM_TOTAL);

    prep_zero_kernel<<<57, 1024>>>();
    prep_proj_kernel<<<64, 256>>>(node, pl0w, pl0b, l1);
    prep_wsplit_kernel<<<952, 256>>>(f1w, f2w);
    e3_main_kernel<<<NE / 128, THREADS, SM_TOTAL>>>(pair, pidx, esh, esrc, edst,
                                                    lng, lnb, f1b, f2b);
    finalize_kernel<<<NNODE, 256>>>(node, l1, pnw, pnb, out);
}

// round 13
// speedup vs baseline: 6.5367x; 1.0570x over previous
#include <cuda_runtime.h>
#include <cuda_fp16.h>
#include <cstdint>

#define B_     4
#define L_     256
#define NNODE  1024
#define DNODE  256
#define DPAIR  128
#define NE     65536
#define M0_    32
#define DIRR   56
#define WNUM_  1664

#define PW0   0.15811388300841897f
#define PW1   0.25f
#define S3C   0.5773502691896258f
#define F121  0.5477225575051661f

// device scratch (no allocations allowed)
__device__ float g_feats[NNODE * DIRR];
__device__ float g_sums [NNODE * DIRR];
__device__ float g_cnt  [NNODE];
// fp16 weights: fc1 plain; fc2 26-chunk 64-col permuted layout, pitch 72
__device__ uint4 g_w1[2176];     // 128 x 136 fp16 = 34,816 B
__device__ uint4 g_w2[29952];    // 26 x 128 x 72 fp16 = 479,232 B

// ---------------- plain-PTX helpers (sm_80-level, safe on sm_103) ----------
__device__ __forceinline__ uint32_t smem_u32(const void* p) {
    uint32_t a;
    asm("{ .reg .u64 t; cvta.to.shared.u64 t, %1; cvt.u32.u64 %0, t; }"
        : "=r"(a) : "l"(p));
    return a;
}
__device__ __forceinline__ void ldsm_x4(uint32_t* r, uint32_t addr) {
    asm volatile("ldmatrix.sync.aligned.m8n8.x4.shared.b16 {%0,%1,%2,%3}, [%4];"
        : "=r"(r[0]), "=r"(r[1]), "=r"(r[2]), "=r"(r[3]) : "r"(addr));
}
__device__ __forceinline__ void ldsm_x4t(uint32_t* r, uint32_t addr) {
    asm volatile("ldmatrix.sync.aligned.m8n8.x4.trans.shared.b16 {%0,%1,%2,%3}, [%4];"
        : "=r"(r[0]), "=r"(r[1]), "=r"(r[2]), "=r"(r[3]) : "r"(addr));
}
__device__ __forceinline__ void mma_f16(float* d, const uint32_t* a,
                                        uint32_t b0, uint32_t b1) {
    asm volatile("mma.sync.aligned.m16n8k16.row.col.f32.f16.f16.f32 "
        "{%0,%1,%2,%3}, {%4,%5,%6,%7}, {%8,%9}, {%0,%1,%2,%3};"
        : "+f"(d[0]), "+f"(d[1]), "+f"(d[2]), "+f"(d[3])
        : "r"(a[0]), "r"(a[1]), "r"(a[2]), "r"(a[3]), "r"(b0), "r"(b1));
}
__device__ __forceinline__ void cpasync16(uint32_t s, const void* g) {
    asm volatile("cp.async.cg.shared.global [%0], [%1], 16;" :: "r"(s), "l"(g));
}
#define CP_COMMIT() asm volatile("cp.async.commit_group;" ::: "memory")
#define CP_WAIT(N)  asm volatile("cp.async.wait_group %0;" :: "n"(N) : "memory")

// smem layout (bytes) -- 64 edges per CTA, 2 CTAs per SM
#define CHUNK_B  18432    // fc2 chunk: 128 rows x 72 fp16 (pitch 144)
#define SM_W     0        // single slot: fc1w halves, then fc2 chunks
#define SM_HHI   18432    // 64 x 136 fp16, pitch 272
#define SM_XLO   35840    // x-lo for fc1 (pitch 272); later F staging 64x64 f32
#define SM_A     53248    // x f32 staging 64x128; then A coeffs 64x185 f32
#define SM_F2B   100608   // 1664 f32
#define SM_F1B   107264   // 128 f32
#define SM_TOTAL 107776

#define THREADS  256
#define APITCH   185

// ---------------------------------------------------------------------------
__global__ void prep_zero_kernel() {
    int i = blockIdx.x * 1024 + threadIdx.x;
    if (i < NNODE * DIRR) g_sums[i] = 0.f;
    else if (i < NNODE * DIRR + NNODE) g_cnt[i - NNODE * DIRR] = 0.f;
}

__global__ __launch_bounds__(256) void prep_proj_kernel(
        const float* __restrict__ node, const float* __restrict__ w,
        const float* __restrict__ b,    const float* __restrict__ l1) {
    __shared__ float sw[DNODE * M0_];
    __shared__ float sx[16 * DNODE];
    int tid = threadIdx.x, n0 = blockIdx.x * 16;
    for (int i = tid; i < DNODE * M0_; i += 256) sw[i] = w[i];
    for (int i = tid; i < 16 * DNODE; i += 256) sx[i] = node[n0 * DNODE + i];
    __syncthreads();
    int warp = tid >> 5, lane = tid & 31;
    for (int r = 0; r < 2; ++r) {
        int nl = warp * 2 + r;
        float acc = b[lane];
        const float* x = sx + nl * DNODE;
#pragma unroll 8
        for (int k = 0; k < DNODE; ++k) acc += x[k] * sw[k * M0_ + lane];
        g_feats[(n0 + nl) * DIRR + lane] = acc;
    }
    for (int i = tid; i < 16 * 24; i += 256) {
        int nl = i / 24, m = i - nl * 24;
        g_feats[(n0 + nl) * DIRR + M0_ + m] = l1[(n0 + nl) * 24 + m];
    }
}

// fc2 26-chunk permutation: chunk c (0..25), band wn (0..1), tile t (0..3),
// slot s (0..7) -> original k
__host__ __device__ __forceinline__ int perm26(int c, int wn, int t, int s) {
    if (c < 16)  return (2 * c + wn) * 32 + t * 8 + s;                 // W1
    if (c < 20)  return 1024 + ((c - 16) * 8 + wn * 4 + t) * 8 + s;    // W2
    if (c == 20) return 1280 + (wn * 4 + t) * 8 + s;                   // W3
    if (c < 25)  return 1344 + ((c - 21) * 2 + wn) * 32 + t * 8 + s;   // W4
    return 1600 + (wn * 4 + t) * 8 + s;                                // W5
}

__global__ void prep_wsplit_kernel(const float* __restrict__ f1w,
                                   const float* __restrict__ f2w) {
    int i = blockIdx.x * 256 + threadIdx.x;
    if (i < 128 * 136) {
        int k = i / 136, n = i - k * 136;
        float v = (n < 128) ? f1w[k * 128 + n] : 0.f;
        ((__half*)g_w1)[i] = __float2half_rn(v);
    } else {
        int j = i - 128 * 136;
        if (j < 26 * 128 * 72) {
            int c = j / (128 * 72), r = j - c * (128 * 72);
            int krow = r / 72, col = r - krow * 72;
            float v = 0.f;
            if (col < 64) {
                int wn = col >> 5, t = (col >> 3) & 3, s = col & 7;
                v = f2w[(size_t)krow * WNUM_ + perm26(c, wn, t, s)];
            }
            ((__half*)g_w2)[(size_t)c * 9216 + krow * 72 + col] =
                __float2half_rn(v);
        }
    }
}

// ---------------------------------------------------------------------------
__launch_bounds__(THREADS, 2) __global__
void e3_main_kernel(const float* __restrict__ pair,
                    const int*   __restrict__ pidx,
                    const float* __restrict__ esh,
                    const int*   __restrict__ esrc,
                    const int*   __restrict__ edst,
                    const float* __restrict__ lng,
                    const float* __restrict__ lnb,
                    const float* __restrict__ f1b,
                    const float* __restrict__ f2b) {
    extern __shared__ char smem[];
    float* sA     = (float*)(smem + SM_A);
    float* sF     = (float*)(smem + SM_XLO);   // F staging (after fc1)
    float* f2b_s  = (float*)(smem + SM_F2B);
    float* f1b_s  = (float*)(smem + SM_F1B);
    const uint32_t smW   = smem_u32(smem + SM_W);
    const uint32_t smHHI = smem_u32(smem + SM_HHI);
    const uint32_t smXLO = smem_u32(smem + SM_XLO);

    const int tid = threadIdx.x, warp = tid >> 5, lane = tid & 31;
    const int eb0 = blockIdx.x * 64;
    const int warp_m = warp & 3, wn = warp >> 2;       // 4m x 2n
    const int gr = lane >> 2, tig = lane & 3;
    const int e0l = warp_m * 16 + gr, e1l = e0l + 8;

#define PREFETCH_CHUNK(cc) do {                                          \
    const char* gsrc_ = (const char*)g_w2 + (size_t)(cc) * CHUNK_B;      \
    _Pragma("unroll")                                                    \
    for (int u_ = 0; u_ < 5; ++u_) {                                     \
        int idx_ = tid + u_ * THREADS;                                   \
        if (idx_ < 1152) cpasync16(smW + idx_ * 16, gsrc_ + idx_ * 16);  \
    }                                                                    \
    CP_COMMIT();                                                         \
} while (0)

#define PREFETCH_W1HALF(p) do {                                          \
    const char* gsrc_ = (const char*)g_w1 + (p) * 17408;                 \
    _Pragma("unroll")                                                    \
    for (int u_ = 0; u_ < 5; ++u_) {                                     \
        int idx_ = tid + u_ * THREADS;                                   \
        if (idx_ < 1088) cpasync16(smW + idx_ * 16, gsrc_ + idx_ * 16);  \
    }                                                                    \
    CP_COMMIT();                                                         \
} while (0)

    // ---- prefetch fc1 weight half 0 -----------------------------------------
    PREFETCH_W1HALF(0);

    // ---- gather x into sA [64][128] f32; copy biases ------------------------
    for (int idx4 = tid; idx4 < 64 * 32; idx4 += THREADS) {
        int el = idx4 >> 5, c4 = idx4 & 31;
        int e = eb0 + el;
        int b = pidx[e], i = pidx[NE + e], j = pidx[2 * NE + e];
        ((float4*)sA)[el * 32 + c4] =
            ((const float4*)(pair + (size_t)(((b * L_) + i) * L_ + j) * DPAIR))[c4];
    }
    for (int i4 = tid; i4 < WNUM_ / 4; i4 += THREADS)
        ((float4*)f2b_s)[i4] = ((const float4*)f2b)[i4];
    if (tid < 128) f1b_s[tid] = f1b[tid];
    __syncthreads();

    // ---- LayerNorm; split x -> HHI / XLO (warp: 8 edges) --------------------
    {
        float g0 = lng[lane], g1 = lng[lane + 32], g2 = lng[lane + 64], g3 = lng[lane + 96];
        float b0 = lnb[lane], b1 = lnb[lane + 32], b2 = lnb[lane + 64], b3 = lnb[lane + 96];
        for (int ee = 0; ee < 8; ++ee) {
            int el = warp * 8 + ee;
            const float* xr = sA + el * 128;
            float x0 = xr[lane], x1 = xr[lane + 32], x2 = xr[lane + 64], x3 = xr[lane + 96];
            float s = x0 + x1 + x2 + x3;
#pragma unroll
            for (int o = 16; o > 0; o >>= 1) s += __shfl_xor_sync(0xffffffffu, s, o);
            float mu = s * (1.f / 128.f);
            float d0 = x0 - mu, d1 = x1 - mu, d2 = x2 - mu, d3 = x3 - mu;
            float q = d0 * d0 + d1 * d1 + d2 * d2 + d3 * d3;
#pragma unroll
            for (int o = 16; o > 0; o >>= 1) q += __shfl_xor_sync(0xffffffffu, q, o);
            float rstd = rsqrtf(q * (1.f / 128.f) + 1e-5f);
            float v[4] = {d0 * rstd * g0 + b0, d1 * rstd * g1 + b1,
                          d2 * rstd * g2 + b2, d3 * rstd * g3 + b3};
#pragma unroll
            for (int p = 0; p < 4; ++p) {
                int col = lane + p * 32;
                __half h = __float2half_rn(v[p]);
                __half l = __float2half_rn(v[p] - __half2float(h));
                *(__half*)(smem + SM_HHI + el * 272 + col * 2) = h;
                *(__half*)(smem + SM_XLO + el * 272 + col * 2) = l;
            }
        }
    }
    CP_WAIT(0);
    __syncthreads();   // x split visible; w1 half0 resident

    // ---- fc1: acc over 2 weight-halves; h = relu(x @ fc1_w + b) -------------
    float acc1[8][4];
#pragma unroll
    for (int t = 0; t < 8; ++t) {
        float2 bv = *(const float2*)&f1b_s[wn * 64 + t * 8 + 2 * tig];
        acc1[t][0] = bv.x; acc1[t][1] = bv.y; acc1[t][2] = bv.x; acc1[t][3] = bv.y;
    }
    const int rowsel = warp_m * 16 + (lane & 15);
    const uint32_t cex = (lane & 16) ? 16 : 0;

    // phase A: k-steps 0..3 (weight rows 0..63)
    {
        uint32_t xa[4][4], xb[4][4];
#pragma unroll
        for (int ks = 0; ks < 4; ++ks) {
            uint32_t off = rowsel * 272 + ks * 32 + cex;
            ldsm_x4(xa[ks], smHHI + off);
            ldsm_x4(xb[ks], smXLO + off);
        }
#pragma unroll
        for (int t = 0; t < 8; ++t) {
            uint32_t col2 = (wn * 64 + t * 8) * 2;
#pragma unroll
            for (int kp = 0; kp < 2; ++kp) {
                uint32_t b4[4];
                ldsm_x4t(b4, smW + (kp * 32 + lane) * 272 + col2);
                mma_f16(acc1[t], xa[2 * kp],     b4[0], b4[1]);
                mma_f16(acc1[t], xa[2 * kp + 1], b4[2], b4[3]);
                mma_f16(acc1[t], xb[2 * kp],     b4[0], b4[1]);
                mma_f16(acc1[t], xb[2 * kp + 1], b4[2], b4[3]);
            }
        }
    }
    __syncthreads();               // slot reads done
    PREFETCH_W1HALF(1);
    CP_WAIT(0);
    __syncthreads();               // w1 half1 resident

    // phase B: k-steps 4..7 (weight rows 64..127)
    {
        uint32_t xa[4][4], xb[4][4];
#pragma unroll
        for (int ks = 0; ks < 4; ++ks) {
            uint32_t off = rowsel * 272 + (4 + ks) * 32 + cex;
            ldsm_x4(xa[ks], smHHI + off);
            ldsm_x4(xb[ks], smXLO + off);
        }
        __syncthreads();           // all frag reads done before HHI overwrite
#pragma unroll
        for (int t = 0; t < 8; ++t) {
            uint32_t col2 = (wn * 64 + t * 8) * 2;
#pragma unroll
            for (int kp = 0; kp < 2; ++kp) {
                uint32_t b4[4];
                ldsm_x4t(b4, smW + (kp * 32 + lane) * 272 + col2);
                mma_f16(acc1[t], xa[2 * kp],     b4[0], b4[1]);
                mma_f16(acc1[t], xa[2 * kp + 1], b4[2], b4[3]);
                mma_f16(acc1[t], xb[2 * kp],     b4[0], b4[1]);
                mma_f16(acc1[t], xb[2 * kp + 1], b4[2], b4[3]);
            }
        }
    }
    // epilogue: relu, store h (hi only)
#pragma unroll
    for (int t = 0; t < 8; ++t) {
        int colb = wn * 64 + t * 8 + 2 * tig;
#pragma unroll
        for (int e = 0; e < 2; ++e) {
            int row = warp_m * 16 + gr + e * 8;
            float v0 = fmaxf(acc1[t][2 * e],     0.f);
            float v1 = fmaxf(acc1[t][2 * e + 1], 0.f);
            *(__half2*)(smem + SM_HHI + row * 272 + colb * 2) =
                __halves2half2(__float2half_rn(v0), __float2half_rn(v1));
        }
    }
    __syncthreads();   // fc1 done: slot free, XLO free, HHI complete

    // ---- prefetch fc2 chunk 0; stage F rows; A coefficients -----------------
    PREFETCH_CHUNK(0);

    // F staging: g_feats rows of edge dsts -> sF (pitch 64 f32)
    for (int idx4 = tid; idx4 < 64 * 16; idx4 += THREADS) {
        int el = idx4 >> 4, q = idx4 & 15;
        if (q < 14)
            ((float4*)sF)[el * 16 + q] =
                ((const float4*)(g_feats + edst[eb0 + el] * DIRR))[q];
    }
    __syncthreads();   // F staged (sync also covers sA x -> A overwrite)

#pragma unroll 1
    for (int ee = 0; ee < 8; ++ee) {
        int el = warp * 8 + ee;
        int e  = eb0 + el;
        const float* F  = sF + el * 64;
        const float* SH = esh + e * 9;
        float* Adst = sA + el * APITCH;
        for (int a = lane; a < 184; a += 32) {
            float val;
            if (a < 32) {
                val = PW0 * F[a] * SH[0];
            } else if (a < 40) {
                int u = a - 32;
                val = (PW0 * S3C) * (F[32 + u * 3] * SH[1] + F[33 + u * 3] * SH[2]
                                     + F[34 + u * 3] * SH[3]);
            } else if (a < 136) {
                int t = a - 40; int u = t / 3, m = t - u * 3;
                val = (PW1 * S3C) * F[u] * SH[1 + m];
            } else if (a < 160) {
                int t = a - 136; int u = t / 3, m = t - u * 3;
                val = (PW1 * S3C) * F[32 + u * 3 + m] * SH[0];
            } else {
                int t = a - 160; int u = t / 3, m = t - u * 3;
                float xx = F[32 + u * 3], xy = F[33 + u * 3], xz = F[34 + u * 3];
                float s0 = SH[4], s1 = SH[5], s2 = SH[6], s3v = SH[7], s4 = SH[8];
                float t5;
                if (m == 0)      t5 = (xz * s0 + xy * s1 - xx * s4) * S3C - xx * s2 * (1.f / 3.f);
                else if (m == 1) t5 = (xx * s1 + xz * s3v) * S3C + xy * s2 * (2.f / 3.f);
                else             t5 = (xx * s0 + xy * s3v + xz * s4) * S3C - xz * s2 * (1.f / 3.f);
                val = (PW1 * F121) * t5;
            }
            Adst[a] = val;
        }
    }

    // h fragments (reused across all 26 chunks)
    uint32_t xh[8][4];
#pragma unroll
    for (int ks = 0; ks < 8; ++ks)
        ldsm_x4(xh[ks], smHHI + rowsel * 272 + ks * 32 + cex);
    __syncthreads();   // A complete

    float conv0[16];
#pragma unroll
    for (int o = 0; o < 16; ++o) conv0[o] = 0.f;
    float conv1[12];
#pragma unroll
    for (int o = 0; o < 12; ++o) conv1[o] = 0.f;
    const float* A0r = sA + e0l * APITCH;
    const float* A1r = sA + e1l * APITCH;

#define CHUNK_MMA(ACC, COL2)                                             \
    { uint32_t b4_[4];                                                   \
      _Pragma("unroll")                                                  \
      for (int kp_ = 0; kp_ < 4; ++kp_) {                                \
          ldsm_x4t(b4_, smW + (kp_ * 32 + lane) * 144 + (COL2));         \
          mma_f16(ACC, xh[2 * kp_],     b4_[0], b4_[1]);                 \
          mma_f16(ACC, xh[2 * kp_ + 1], b4_[2], b4_[3]);                 \
      } }

    // ---- W1: chunks 0..15 -> conv0 ------------------------------------------
#pragma unroll 1
    for (int c = 0; c < 16; ++c) {
        CP_WAIT(0); __syncthreads();
        const int u = 2 * c + wn;
        float a0 = A0r[u], a1 = A1r[u];
#pragma unroll
        for (int t = 0; t < 4; ++t) {
            float2 bv = *(const float2*)&f2b_s[u * 32 + t * 8 + 2 * tig];
            float acc[4] = {bv.x, bv.y, bv.x, bv.y};
            CHUNK_MMA(acc, (wn * 32 + t * 8) * 2);
            conv0[t * 4 + 0] += a0 * acc[0]; conv0[t * 4 + 1] += a0 * acc[1];
            conv0[t * 4 + 2] += a1 * acc[2]; conv0[t * 4 + 3] += a1 * acc[3];
        }
        __syncthreads();
        PREFETCH_CHUNK(c + 1);
    }
    // ---- W2: chunks 16..19 -> conv1 ------------------------------------------
#pragma unroll 1
    for (int c = 16; c < 20; ++c) {
        CP_WAIT(0); __syncthreads();
        const int ub = (c - 16) * 8 + wn * 4;
#pragma unroll
        for (int t = 0; t < 4; ++t) {
            const int u = ub + t;
            float2 bv = *(const float2*)&f2b_s[1024 + u * 8 + 2 * tig];
            float acc[4] = {bv.x, bv.y, bv.x, bv.y};
            CHUNK_MMA(acc, (wn * 32 + t * 8) * 2);
            const float* A0 = A0r + 40 + u * 3;
            const float* A1 = A1r + 40 + u * 3;
#pragma unroll
            for (int m = 0; m < 3; ++m) {
                conv1[m]     += A0[m] * acc[0];
                conv1[3 + m] += A0[m] * acc[1];
                conv1[6 + m] += A1[m] * acc[2];
                conv1[9 + m] += A1[m] * acc[3];
            }
        }
        __syncthreads();
        PREFETCH_CHUNK(c + 1);
    }
    // ---- W3: chunk 20 -> conv1 ------------------------------------------------
    {
        CP_WAIT(0); __syncthreads();
#pragma unroll
        for (int t = 0; t < 4; ++t) {
            const int u = wn * 4 + t;
            float2 bv = *(const float2*)&f2b_s[1280 + u * 8 + 2 * tig];
            float acc[4] = {bv.x, bv.y, bv.x, bv.y};
            CHUNK_MMA(acc, (wn * 32 + t * 8) * 2);
            const float* A0 = A0r + 136 + u * 3;
            const float* A1 = A1r + 136 + u * 3;
#pragma unroll
            for (int m = 0; m < 3; ++m) {
                conv1[m]     += A0[m] * acc[0];
                conv1[3 + m] += A0[m] * acc[1];
                conv1[6 + m] += A1[m] * acc[2];
                conv1[9 + m] += A1[m] * acc[3];
            }
        }
        __syncthreads();
        PREFETCH_CHUNK(21);
    }
    // ---- W4: chunks 21..24 -> conv0 --------------------------------------------
#pragma unroll 1
    for (int c = 21; c < 25; ++c) {
        CP_WAIT(0); __syncthreads();
        const int uu = (c - 21) * 2 + wn;
        float a0 = A0r[32 + uu], a1 = A1r[32 + uu];
#pragma unroll
        for (int t = 0; t < 4; ++t) {
            float2 bv = *(const float2*)&f2b_s[1344 + uu * 32 + t * 8 + 2 * tig];
            float acc[4] = {bv.x, bv.y, bv.x, bv.y};
            CHUNK_MMA(acc, (wn * 32 + t * 8) * 2);
            conv0[t * 4 + 0] += a0 * acc[0]; conv0[t * 4 + 1] += a0 * acc[1];
            conv0[t * 4 + 2] += a1 * acc[2]; conv0[t * 4 + 3] += a1 * acc[3];
        }
        __syncthreads();
        PREFETCH_CHUNK(c + 1);
    }
    // ---- W5: chunk 25 -> conv1 --------------------------------------------------
    {
        CP_WAIT(0); __syncthreads();
#pragma unroll
        for (int t = 0; t < 4; ++t) {
            const int u = wn * 4 + t;
            float2 bv = *(const float2*)&f2b_s[1600 + u * 8 + 2 * tig];
            float acc[4] = {bv.x, bv.y, bv.x, bv.y};
            CHUNK_MMA(acc, (wn * 32 + t * 8) * 2);
            const float* A0 = A0r + 160 + u * 3;
            const float* A1 = A1r + 160 + u * 3;
#pragma unroll
            for (int m = 0; m < 3; ++m) {
                conv1[m]     += A0[m] * acc[0];
                conv1[3 + m] += A0[m] * acc[1];
                conv1[6 + m] += A1[m] * acc[2];
                conv1[9 + m] += A1[m] * acc[3];
            }
        }
    }

    // ---- epilogue: scatter-add -----------------------------------------------
    {
        int s0 = esrc[eb0 + e0l] * DIRR;
        int s1 = esrc[eb0 + e1l] * DIRR;
#pragma unroll
        for (int t = 0; t < 4; ++t)
#pragma unroll
            for (int j = 0; j < 2; ++j) {
                int v = t * 8 + 2 * tig + j;
                atomicAdd(&g_sums[s0 + v], conv0[t * 4 + j]);
                atomicAdd(&g_sums[s1 + v], conv0[t * 4 + 2 + j]);
            }
#pragma unroll
        for (int j = 0; j < 2; ++j)
#pragma unroll
            for (int m = 0; m < 3; ++m) {
                int o = 32 + (2 * tig + j) * 3 + m;
                atomicAdd(&g_sums[s0 + o], conv1[j * 3 + m]);
                atomicAdd(&g_sums[s1 + o], conv1[6 + j * 3 + m]);
            }
    }
    if (tid < 64) atomicAdd(&g_cnt[esrc[eb0 + tid]], 1.f);
}

// ---------------------------------------------------------------------------
__global__ void finalize_kernel(const float* __restrict__ node,
                                const float* __restrict__ l1,
                                const float* __restrict__ pnw,
                                const float* __restrict__ pnb,
                                float* __restrict__ out) {
    int n = blockIdx.x;
    __shared__ float o0[32];
    float inv = 1.f / fmaxf(g_cnt[n], 1.f);
    if (threadIdx.x < 32) o0[threadIdx.x] = g_sums[n * DIRR + threadIdx.x] * inv;
    __syncthreads();
    int d = threadIdx.x;
    float acc = pnb[d];
#pragma unroll
    for (int u = 0; u < 32; ++u) acc += o0[u] * pnw[u * DNODE + d];
    out[n * DNODE + d] = acc + node[n * DNODE + d];
    if (d < 24)
        out[NNODE * DNODE + n * 24 + d] = g_sums[n * DIRR + 32 + d] * inv + l1[n * 24 + d];
}

// ---------------------------------------------------------------------------
extern "C" void kernel_launch(void* const* d_in, const int* in_sizes, int n_in,
                              void* d_out, int out_size) {
    const float* node = (const float*)d_in[0];
    const float* pair = (const float*)d_in[1];
    const float* l1   = (const float*)d_in[2];
    const float* esh  = (const float*)d_in[3];
    const float* pl0w = (const float*)d_in[4];
    const float* pl0b = (const float*)d_in[5];
    const float* pnw  = (const float*)d_in[6];
    const float* pnb  = (const float*)d_in[7];
    const float* lng  = (const float*)d_in[8];
    const float* lnb  = (const float*)d_in[9];
    const float* f1w  = (const float*)d_in[10];
    const float* f1b  = (const float*)d_in[11];
    const float* f2w  = (const float*)d_in[12];
    const float* f2b  = (const float*)d_in[13];
    const int*   pidx = (const int*)d_in[14];
    const int*   esrc = (const int*)d_in[15];
    const int*   edst = (const int*)d_in[16];
    float* out = (float*)d_out;

    cudaFuncSetAttribute(e3_main_kernel,
                         cudaFuncAttributeMaxDynamicSharedMemorySize, SM_TOTAL);

    prep_zero_kernel<<<57, 1024>>>();
    prep_proj_kernel<<<64, 256>>>(node, pl0w, pl0b, l1);
    prep_wsplit_kernel<<<1004, 256>>>(f1w, f2w);
    e3_main_kernel<<<NE / 64, THREADS, SM_TOTAL>>>(pair, pidx, esh, esrc, edst,
                                                   lng, lnb, f1b, f2b);
    finalize_kernel<<<NNODE, 256>>>(node, l1, pnw, pnb, out);
}